// round 13
// baseline (speedup 1.0000x reference)
#include <cuda_runtime.h>
#include <cstdint>

#define BATCH   8
#define NLEV    3
#define NCLS    80
#define TOPK    1000
#define NCAND   3000
#define DETS    100
#define CAPC    32768
#define NBINS   16384
#define IMGSZ   2048.0f
#define SCORE_TH 0.2f
#define NMS_TH   0.6f
#define BIN_SCALE 9216.0f
#define G_HI    (1.0f + (float)NBINS/BIN_SCALE)
#define EPT     16
#define EPT2    32
#define SENT    0x7FFFFFFF

#define HW0 4096
#define HW1 1024
#define HW2 256
#define E0  (HW0*NCLS)
#define E1  (HW1*NCLS)
#define E2  (HW2*NCLS)
#define TOT (BATCH*(E0+E1+E2))

typedef unsigned long long ull;

// conservative per-level collection bins (s >= ~0.73 / 0.70 / 0.62)
static __constant__ int c_prebin[NLEV] = { 8078, 9592, 14760 };

// -------- scratch (zero-init; self-cleaned each replay) --------
static __device__ __align__(16) unsigned int g_hist[BATCH*NLEV*NBINS];
static __device__ unsigned int   g_cnt[BATCH*NLEV];
static __device__ ull            g_cand[BATCH*NLEV*CAPC];
static __device__ unsigned short g_binv[BATCH*NLEV*CAPC];
static __device__ float   g_score[BATCH*NCAND];
static __device__ int     g_label[BATCH*NCAND];
static __device__ float4  g_box[BATCH*NCAND];

__device__ __forceinline__ float sigm(float x){ return 1.0f/(1.0f+expf(-x)); }
__device__ __forceinline__ unsigned int fkey(float f){
    unsigned int u = __float_as_uint(f);
    return (u & 0x80000000u) ? ~u : (u | 0x80000000u);
}
__device__ __forceinline__ float keyToFloat(unsigned int k){
    unsigned int u = (k & 0x80000000u) ? (k & 0x7FFFFFFFu) : ~k;
    return __uint_as_float(u);
}
__device__ __forceinline__ int binOf(float g){
    return (int)(fmaxf(g - 1.0f, 0.0f) * BIN_SCALE);
}
__device__ __forceinline__ ull umin64(ull a, ull b){ return a < b ? a : b; }
__device__ __forceinline__ ull umax64(ull a, ull b){ return a > b ? a : b; }

struct Seg { int img, lvl, e, HW, E; };
__device__ __forceinline__ Seg decompose(int gid){
    Seg s;
    if (gid < BATCH*E0){ s.lvl=0; s.img=gid/E0; s.e=gid%E0; s.HW=HW0; s.E=E0; return s; }
    gid -= BATCH*E0;
    if (gid < BATCH*E1){ s.lvl=1; s.img=gid/E1; s.e=gid%E1; s.HW=HW1; s.E=E1; return s; }
    gid -= BATCH*E1;
    s.lvl=2; s.img=gid/E2; s.e=gid%E2; s.HW=HW2; s.E=E2; return s;
}

// ======== K1: 32 elems/thread; fmax screen per 16-half; collect bin <= prebin ========
#define SBUF 1024
#define STHREADS 128
__global__ void __launch_bounds__(STHREADS, 1)
k_score(const float* __restrict__ cls0,const float* __restrict__ cls1,const float* __restrict__ cls2,
        const float* __restrict__ ctr0,const float* __restrict__ ctr1,const float* __restrict__ ctr2){
    __shared__ ull            sbuf[SBUF];
    __shared__ unsigned short sbin[SBUF];
    __shared__ int sN, sBase;
    int tid = threadIdx.x;
    if (tid == 0) sN = 0;
    __syncthreads();
    int gid = (blockIdx.x*STHREADS + tid)*EPT2;
    Seg S = decompose(gid);              // one block = 4096 contiguous elems, single IL
    const float* cls = (S.lvl==0)?cls0:(S.lvl==1)?cls1:cls2;
    const float* ctr = (S.lvl==0)?ctr0:(S.lvl==1)?ctr1:ctr2;
    int IL = S.img*NLEV + S.lvl;
    size_t ILc = (size_t)IL*CAPC;
    int prebin = c_prebin[S.lvl];
    const float4* cp = reinterpret_cast<const float4*>(&cls[S.img*S.E + S.e]);
    float4 c0 = cp[0], c1 = cp[1], c2 = cp[2], c3 = cp[3];
    float4 c4 = cp[4], c5 = cp[5], c6 = cp[6], c7 = cp[7];
    // 16-halves never cross an anchor (boundaries at multiples of 16)
    int a0 = S.e / NCLS;
    int a1 = (S.e + 16) / NCLS;
    float tv0 = ctr[S.img*S.HW + a0];
    float tv1 = (a1 == a0) ? tv0 : ctr[S.img*S.HW + a1];
    float K0 = 1.0f + __expf(-tv0);
    float K1 = (a1 == a0) ? K0 : 1.0f + __expf(-tv1);
    float gpre = 1.0f + (float)(prebin+1)/BIN_SCALE;
    float q0 = __fdividef(gpre, K0);
    float Tc0 = (q0 <= 1.0f) ? 3.0e38f : (-__logf(q0 - 1.0f) - 1e-3f);
    float q1 = __fdividef(gpre, K1);
    float Tc1 = (q1 <= 1.0f) ? 3.0e38f : (-__logf(q1 - 1.0f) - 1e-3f);
    unsigned int* H = &g_hist[IL*NBINS];
    int lane = tid & 31;

    // group max per half -> two screening compares
    float m0 = fmaxf(fmaxf(fmaxf(c0.x,c0.y), fmaxf(c0.z,c0.w)),
                     fmaxf(fmaxf(c1.x,c1.y), fmaxf(c1.z,c1.w)));
    float m1 = fmaxf(fmaxf(fmaxf(c2.x,c2.y), fmaxf(c2.z,c2.w)),
                     fmaxf(fmaxf(c3.x,c3.y), fmaxf(c3.z,c3.w)));
    float max0 = fmaxf(m0, m1);
    float m2 = fmaxf(fmaxf(fmaxf(c4.x,c4.y), fmaxf(c4.z,c4.w)),
                     fmaxf(fmaxf(c5.x,c5.y), fmaxf(c5.z,c5.w)));
    float m3 = fmaxf(fmaxf(fmaxf(c6.x,c6.y), fmaxf(c6.z,c6.w)),
                     fmaxf(fmaxf(c7.x,c7.y), fmaxf(c7.z,c7.w)));
    float max1 = fmaxf(m2, m3);

    unsigned hitmask = 0;
    float cv[EPT2];
    bool any0 = (max0 > Tc0), any1 = (max1 > Tc1);
    if (any0 | any1){
        cv[0]=c0.x; cv[1]=c0.y; cv[2]=c0.z; cv[3]=c0.w;
        cv[4]=c1.x; cv[5]=c1.y; cv[6]=c1.z; cv[7]=c1.w;
        cv[8]=c2.x; cv[9]=c2.y; cv[10]=c2.z; cv[11]=c2.w;
        cv[12]=c3.x; cv[13]=c3.y; cv[14]=c3.z; cv[15]=c3.w;
        cv[16]=c4.x; cv[17]=c4.y; cv[18]=c4.z; cv[19]=c4.w;
        cv[20]=c5.x; cv[21]=c5.y; cv[22]=c5.z; cv[23]=c5.w;
        cv[24]=c6.x; cv[25]=c6.y; cv[26]=c6.z; cv[27]=c6.w;
        cv[28]=c7.x; cv[29]=c7.y; cv[30]=c7.z; cv[31]=c7.w;
        if (any0){
            #pragma unroll
            for (int i = 0; i < 16; i++){
                if (cv[i] > Tc0){
                    float g = fmaf(__expf(-cv[i]), K0, K0);   // exact same bin formula everywhere
                    int b = binOf(g);
                    if (b <= prebin){ atomicAdd(&H[b], 1u); hitmask |= (1u << i); }
                }
            }
        }
        if (any1){
            #pragma unroll
            for (int i = 16; i < 32; i++){
                if (cv[i] > Tc1){
                    float g = fmaf(__expf(-cv[i]), K1, K1);
                    int b = binOf(g);
                    if (b <= prebin){ atomicAdd(&H[b], 1u); hitmask |= (1u << i); }
                }
            }
        }
    }

    // one warp scan for write positions
    int nloc = __popc(hitmask);
    unsigned incs = (unsigned)nloc;
    #pragma unroll
    for (int o = 1; o < 32; o <<= 1){
        unsigned v = __shfl_up_sync(0xFFFFFFFFu, incs, o);
        if (lane >= o) incs += v;
    }
    int wtot = __shfl_sync(0xFFFFFFFFu, (int)incs, 31);
    int wbase = 0;
    if (wtot){
        if (lane == 31) wbase = atomicAdd(&sN, wtot);
        wbase = __shfl_sync(0xFFFFFFFFu, wbase, 31);
    }
    int p = wbase + (int)incs - nloc;

    // rare writes (static-index recompute)
    if (hitmask){
        #pragma unroll
        for (int i = 0; i < EPT2; i++){
            if (hitmask & (1u << i)){
                float Kx = (i < 16) ? K0 : K1;
                float tvx = (i < 16) ? tv0 : tv1;
                float g = fmaf(__expf(-cv[i]), Kx, Kx);
                int b = binOf(g);
                float sex = sqrtf(sigm(cv[i]) * sigm(tvx));   // exact reference score
                ull word = ~(((ull)fkey(sex) << 32) | (unsigned)(0xFFFFFFFFu - (unsigned)(S.e + i)));
                if (p < SBUF){ sbuf[p] = word; sbin[p] = (unsigned short)b; }
                else {
                    unsigned gp2 = atomicAdd(&g_cnt[IL], 1u);    // rare spill
                    if (gp2 < CAPC){ g_cand[ILc + gp2] = word; g_binv[ILc + gp2] = (unsigned short)b; }
                }
                p++;
            }
        }
    }
    __syncthreads();
    int n = min(sN, SBUF);
    if (tid == 0) sBase = (int)atomicAdd(&g_cnt[IL], (unsigned)n);
    __syncthreads();
    int base = sBase;
    for (int i = tid; i < n; i += STHREADS){
        int gp2 = base + i;
        if (gp2 < CAPC){ g_cand[ILc + gp2] = sbuf[i]; g_binv[ILc + gp2] = sbin[i]; }
    }
}

// decode + clip + store one candidate
__device__ __forceinline__ void emit_cand(int img,int lvl,int r,int e,float score,
                                          const float* reg,const float* anc,int HW){
    int a = e / NCLS, lab = e % NCLS;
    float4 A = reinterpret_cast<const float4*>(anc)[a];
    float4 R = reinterpret_cast<const float4*>(reg)[img*HW + a];
    float cx = 0.5f*(A.x + A.z), cy = 0.5f*(A.y + A.w);
    float w = A.z - A.x, h = A.w - A.y;
    float x0 = fminf(fmaxf(cx - R.x*w, 0.0f), IMGSZ);
    float y0 = fminf(fmaxf(cy - R.y*h, 0.0f), IMGSZ);
    float x1 = fminf(fmaxf(cx + R.z*w, 0.0f), IMGSZ);
    float y1 = fminf(fmaxf(cy + R.w*h, 0.0f), IMGSZ);
    int g = img*NCAND + lvl*TOPK + r;
    g_score[g] = score;
    g_label[g] = lab;
    g_box[g]   = make_float4(x0,y0,x1,y1);
}

__device__ __forceinline__ void reg_substeps(ull &v0, ull &v1, int k, int jhi, int t){
    bool up = (((2*t) & k) == 0);
    for (int j = jhi; j >= 2; j >>= 1){
        int d = j >> 1;
        ull p0 = __shfl_xor_sync(0xFFFFFFFFu, v0, d);
        ull p1 = __shfl_xor_sync(0xFFFFFFFFu, v1, d);
        bool keepmin = (((t & d) == 0) == up);
        v0 = keepmin ? umin64(v0,p0) : umax64(v0,p0);
        v1 = keepmin ? umin64(v1,p1) : umax64(v1,p1);
    }
    ull a = umin64(v0,v1), b = umax64(v0,v1);
    v0 = up ? a : b;
    v1 = up ? b : a;
}

// parallel histogram scan + clean; writes bstar (or SENT) into *s_bstar.
__device__ __forceinline__ void hist_scan_clean(unsigned int* h, unsigned* wsum,
                                                volatile int* s_bstar,
                                                int t, int lane, int wid){
    uint4* hv = reinterpret_cast<uint4*>(h + t*16);
    uint4 a0 = hv[0], a1 = hv[1], a2 = hv[2], a3 = hv[3];
    unsigned vals[16] = {a0.x,a0.y,a0.z,a0.w, a1.x,a1.y,a1.z,a1.w,
                         a2.x,a2.y,a2.z,a2.w, a3.x,a3.y,a3.z,a3.w};
    unsigned s = 0;
    #pragma unroll
    for (int i = 0; i < 16; i++) s += vals[i];
    unsigned inc = s;
    #pragma unroll
    for (int o = 1; o < 32; o <<= 1){
        unsigned v = __shfl_up_sync(0xFFFFFFFFu, inc, o);
        if (lane >= o) inc += v;
    }
    if (lane == 31) wsum[wid] = inc;
    __syncthreads();
    if (wid == 0){
        unsigned winc = wsum[lane];
        #pragma unroll
        for (int o = 1; o < 32; o <<= 1){
            unsigned v = __shfl_up_sync(0xFFFFFFFFu, winc, o);
            if (lane >= o) winc += v;
        }
        wsum[lane] = winc;
    }
    __syncthreads();
    unsigned below = ((wid == 0) ? 0u : wsum[wid-1]) + (inc - s);
    if (below < TOPK && below + s >= TOPK){
        unsigned cum = below;
        #pragma unroll
        for (int i = 0; i < 16; i++){
            cum += vals[i];
            if (cum >= TOPK){ *s_bstar = t*16 + i; break; }
        }
    }
    uint4 z4 = make_uint4(0,0,0,0);
    hv[0] = z4; hv[1] = z4; hv[2] = z4; hv[3] = z4;
    __syncthreads();
}

// ======== K2: cutoff + compact (or full-rescan fallback) + sort + emit ========
__global__ void __launch_bounds__(1024, 1)
k_levelsort(const float* __restrict__ cls0,const float* __restrict__ cls1,const float* __restrict__ cls2,
            const float* __restrict__ ctr0,const float* __restrict__ ctr1,const float* __restrict__ ctr2,
            const float* __restrict__ reg0,const float* __restrict__ reg1,const float* __restrict__ reg2,
            const float* __restrict__ anc0,const float* __restrict__ anc1,const float* __restrict__ anc2){
    __shared__ ull sh[4096];
    __shared__ unsigned wsum[32];
    __shared__ int s_bstar, s_cnt, s_in;
    cudaGridDependencySynchronize();
    int img = blockIdx.x / NLEV, lvl = blockIdx.x % NLEV;
    int IL = img*NLEV + lvl;
    int t = threadIdx.x, lane = t & 31, wid = t >> 5;
    unsigned int* h = &g_hist[IL*NBINS];

    if (t == 0){
        s_bstar = SENT;
        s_in  = (int)g_cnt[IL];
        g_cnt[IL] = 0u;
        s_cnt = 0;
    }
    __syncthreads();
    hist_scan_clean(h, wsum, &s_bstar, t, lane, wid);
    int bstar = s_bstar;
    int cnt   = s_in;

    const float *reg, *anc, *cls, *ctr; int HW, E;
    if (lvl == 0){ reg=reg0; anc=anc0; cls=cls0; ctr=ctr0; HW=HW0; E=E0; }
    else if (lvl == 1){ reg=reg1; anc=anc1; cls=cls1; ctr=ctr1; HW=HW1; E=E1; }
    else { reg=reg2; anc=anc2; cls=cls2; ctr=ctr2; HW=HW2; E=E2; }

    bool fast = (bstar != SENT) && (bstar <= c_prebin[lvl]) && (cnt <= CAPC);
    size_t ILc = (size_t)IL*CAPC;
    if (fast){
        int n = cnt;
        int nPad = (n + 1023) & ~1023;
        for (int i = t; i < nPad; i += 1024){
            bool keep = (i < n) && (g_binv[ILc + i] <= (unsigned short)bstar);
            ull w = keep ? g_cand[ILc + i] : 0;
            unsigned ball = __ballot_sync(0xFFFFFFFFu, keep);
            int nw = __popc(ball);
            if (nw){
                int bpos = 0;
                if (lane == 0) bpos = atomicAdd(&s_cnt, nw);
                bpos = __shfl_sync(0xFFFFFFFFu, bpos, 0);
                if (keep){
                    int p = bpos + __popc(ball & ((1u << lane) - 1u));
                    if (p < 4096) sh[p] = w;
                }
            }
        }
    } else {
        // ---- fallback (statistically dead, fully correct) ----
        int groups = E / EPT;
        for (int G = t; G < groups; G += 1024){
            int e0 = G*EPT;
            int a = G / 5;                           // 80 = 5*16
            float tval = ctr[img*HW + a];
            float K = 1.0f + __expf(-tval);
            float q2 = __fdividef(G_HI, K);
            float TcF = (q2 <= 1.0f) ? 3.0e38f : (-__logf(q2 - 1.0f) - 1e-3f);
            const float4* cp = reinterpret_cast<const float4*>(&cls[img*E + e0]);
            float4 c0 = cp[0], c1 = cp[1], c2 = cp[2], c3 = cp[3];
            float cv[EPT] = {c0.x,c0.y,c0.z,c0.w, c1.x,c1.y,c1.z,c1.w,
                             c2.x,c2.y,c2.z,c2.w, c3.x,c3.y,c3.z,c3.w};
            #pragma unroll
            for (int i = 0; i < EPT; i++){
                if (cv[i] > TcF){
                    float g = fmaf(__expf(-cv[i]), K, K);
                    int b = binOf(g);
                    if (b < NBINS) atomicAdd(&h[b], 1u);
                }
            }
        }
        __syncthreads();
        if (t == 0) s_bstar = SENT;
        __syncthreads();
        hist_scan_clean(h, wsum, &s_bstar, t, lane, wid);
        bstar = s_bstar;
        for (int G = t; G < groups; G += 1024){
            int e0 = G*EPT;
            int a = G / 5;
            float tval = ctr[img*HW + a];
            float K = 1.0f + __expf(-tval);
            float thrv;
            if (bstar == SENT) thrv = -3.0e38f;
            else {
                float Gm = (1.0f + (float)(bstar+1)/BIN_SCALE) * 1.003f;
                float qr = Gm / K;
                thrv = (qr <= 1.0000012f) ? 3.0e38f : (-logf(qr - 1.0f) - 0.003f);
            }
            const float4* cp = reinterpret_cast<const float4*>(&cls[img*E + e0]);
            float4 c0 = cp[0], c1 = cp[1], c2 = cp[2], c3 = cp[3];
            float cv[EPT] = {c0.x,c0.y,c0.z,c0.w, c1.x,c1.y,c1.z,c1.w,
                             c2.x,c2.y,c2.z,c2.w, c3.x,c3.y,c3.z,c3.w};
            #pragma unroll
            for (int i = 0; i < EPT; i++){
                if (cv[i] > thrv){
                    bool mem = true;
                    if (bstar != SENT){
                        float g = fmaf(__expf(-cv[i]), K, K);
                        mem = (binOf(g) <= bstar);
                    }
                    if (mem){
                        float sex = sqrtf(sigm(cv[i]) * sigm(tval));
                        if (bstar != SENT || sex > SCORE_TH){
                            ull w = ~(((ull)fkey(sex) << 32) | (unsigned)(0xFFFFFFFFu - (unsigned)(e0 + i)));
                            int p = atomicAdd(&s_cnt, 1);
                            if (p < 4096) sh[p] = w;
                        }
                    }
                }
            }
        }
    }
    __syncthreads();
    int C = min(s_cnt, 4096);
    int N = (C <= 1024) ? 1024 : (C <= 2048 ? 2048 : 4096);
    for (int i = C + t; i < N; i += 1024) sh[i] = ~0ULL;
    __syncthreads();

    // ---- hybrid shuffle/smem bitonic sort of N ----
    if (N <= 2048){
        int half = N >> 1;
        ull v0 = 0, v1 = 0;
        if (t < half){
            v0 = sh[2*t]; v1 = sh[2*t+1];
            #pragma unroll
            for (int k = 2; k <= 64; k <<= 1)
                reg_substeps(v0, v1, k, (k>>1) >= 2 ? (k>>1) : 0, t);
            sh[2*t] = v0; sh[2*t+1] = v1;
        }
        __syncthreads();
        for (int k = 128; k <= N; k <<= 1){
            for (int j = k>>1; j >= 64; j >>= 1){
                for (int i = t; i < N; i += 1024){
                    int l = i ^ j;
                    if (l > i){
                        ull a = sh[i], b = sh[l];
                        bool up = ((i & k) == 0);
                        if ((a > b) == up){ sh[i] = b; sh[l] = a; }
                    }
                }
                __syncthreads();
            }
            if (t < half){
                v0 = sh[2*t]; v1 = sh[2*t+1];
                reg_substeps(v0, v1, k, 32, t);
                sh[2*t] = v0; sh[2*t+1] = v1;
            }
            __syncthreads();
        }
    } else {
        for (int k = 2; k <= N; k <<= 1)
            for (int j = k>>1; j > 0; j >>= 1){
                for (int i = t; i < N; i += 1024){
                    int l = i ^ j;
                    if (l > i){
                        ull a = sh[i], b = sh[l];
                        bool up = ((i & k) == 0);
                        if ((a > b) == up){ sh[i] = b; sh[l] = a; }
                    }
                }
                __syncthreads();
            }
    }

    int validK = min(C, TOPK);
    for (int r = t; r < validK; r += 1024){
        ull comb = ~sh[r];
        unsigned key = (unsigned)(comb >> 32);
        int e = (int)(0xFFFFFFFFu - (unsigned)comb);
        emit_cand(img, lvl, r, e, keyToFloat(key), reg, anc, HW);
    }
    if (validK < TOPK && t < 32){
        int nfill = TOPK - validK;
        int cum = 0;
        for (int b = 0; b < E && cum < nfill; b += 32){
            int e = b + t;
            bool fail = false;
            if (e < E){
                float sc2 = sqrtf(sigm(cls[(long long)img*E + e]) * sigm(ctr[img*HW + e/NCLS]));
                fail = !(sc2 > SCORE_TH);
            }
            unsigned bal = __ballot_sync(0xFFFFFFFFu, fail);
            int pre = __popc(bal & ((1u << t) - 1u));
            if (fail && cum + pre < nfill)
                emit_cand(img, lvl, validK + cum + pre, e, -1.0f, reg, anc, HW);
            cum += __popc(bal);
        }
    }
}

// ======== K3: binary-search merge of 3 sorted lists + warp NMS + output ========
#define NMT 512
#define OFF_KEY  0
#define OFF_SC   12000
#define OFF_AR   24000
#define OFF_GID  36000
#define OFF_OB   48000
#define OFF_KP   96000
#define OFF_POS  99000
#define OFF_CTL  99400
#define SMEM_NMS 99424

__global__ void __launch_bounds__(NMT, 1)
k_merge_nms(float* __restrict__ out){
    extern __shared__ char dyn[];
    unsigned int*   skey = (unsigned int*)(dyn + OFF_KEY);
    float*          s_sc = (float*)(dyn + OFF_SC);
    float*          s_ar = (float*)(dyn + OFF_AR);
    int*            s_gid= (int*)(dyn + OFF_GID);
    float4*         s_ob = (float4*)(dyn + OFF_OB);
    unsigned char*  kp   = (unsigned char*)(dyn + OFF_KP);
    int*            pos  = (int*)(dyn + OFF_POS);
    int*            ctl  = (int*)(dyn + OFF_CTL);
    cudaGridDependencySynchronize();
    int img = blockIdx.x, t = threadIdx.x;
    int lane = t & 31;

    #pragma unroll
    for (int k = 0; k < 6; k++){
        int i = t + k*NMT;
        if (i < NCAND){
            skey[i] = fkey(g_score[img*NCAND + i]);
            kp[i] = 0;
        }
    }
    __syncthreads();

    #pragma unroll
    for (int k = 0; k < 6; k++){
        int i = t + k*NMT;
        if (i < NCAND){
            int L = i / TOPK, r = i - L*TOPK;
            unsigned key = skey[i];
            int m = r;
            #pragma unroll
            for (int M = 0; M < NLEV; M++){
                if (M == L) continue;
                const unsigned* a2 = &skey[M*TOPK];
                int lo = 0, hi = TOPK;
                if (M < L){
                    while (lo < hi){ int mid = (lo+hi)>>1; if (a2[mid] >= key) lo = mid+1; else hi = mid; }
                } else {
                    while (lo < hi){ int mid = (lo+hi)>>1; if (a2[mid] >  key) lo = mid+1; else hi = mid; }
                }
                m += lo;
            }
            s_sc[m]  = keyToFloat(key);
            s_gid[m] = i;
            float4 b = g_box[img*NCAND + i];
            float off = (IMGSZ + 1.0f) * (float)g_label[img*NCAND + i];
            float4 ob = make_float4(b.x+off, b.y+off, b.z+off, b.w+off);
            s_ob[m] = ob;
            s_ar[m] = (ob.z - ob.x) * (ob.w - ob.y);
        }
    }
    __syncthreads();

    if (t < 32){
        float kx0[4], ky0[4], kx1[4], ky1[4], kar[4];
        int cnt = 0;
        float  sc_n = s_sc[0];
        float4 bx_n = s_ob[0];
        float  ax_n = s_ar[0];
        for (int ii = 0; ii < NCAND; ii++){
            float sc = sc_n; float4 bx = bx_n; float ax = ax_n;
            if (ii + 1 < NCAND){ sc_n = s_sc[ii+1]; bx_n = s_ob[ii+1]; ax_n = s_ar[ii+1]; }
            if (!(sc > 0.0f)) break;
            bool sup = false;
            #pragma unroll
            for (int s2 = 0; s2 < 4; s2++){
                if (s2*32 + lane < cnt){
                    float xx0 = fmaxf(bx.x, kx0[s2]), yy0 = fmaxf(bx.y, ky0[s2]);
                    float xx1 = fminf(bx.z, kx1[s2]), yy1 = fminf(bx.w, ky1[s2]);
                    float iw = xx1 - xx0, ih = yy1 - yy0;
                    if (iw > 0.0f && ih > 0.0f){
                        float inter = iw * ih;
                        if (inter / (ax + kar[s2] - inter) > NMS_TH) sup = true;
                    }
                }
            }
            if (__any_sync(0xFFFFFFFFu, sup)) continue;
            if (lane == 0){ pos[cnt] = ii; kp[ii] = 1; }
            if (lane == (cnt & 31)){
                int sl = cnt >> 5;
                if      (sl == 0){ kx0[0]=bx.x; ky0[0]=bx.y; kx1[0]=bx.z; ky1[0]=bx.w; kar[0]=ax; }
                else if (sl == 1){ kx0[1]=bx.x; ky0[1]=bx.y; kx1[1]=bx.z; ky1[1]=bx.w; kar[1]=ax; }
                else if (sl == 2){ kx0[2]=bx.x; ky0[2]=bx.y; kx1[2]=bx.z; ky1[2]=bx.w; kar[2]=ax; }
                else             { kx0[3]=bx.x; ky0[3]=bx.y; kx1[3]=bx.z; ky1[3]=bx.w; kar[3]=ax; }
            }
            cnt++;
            if (cnt >= DETS) break;
        }
        if (lane == 0) ctl[0] = cnt;
    }
    __syncthreads();
    int cntF = ctl[0];
    if (t == 0 && cntF < DETS){
        int fill = cntF;
        for (int p = 0; p < NCAND && fill < DETS; p++)
            if (!kp[p]) pos[fill++] = p;
    }
    __syncthreads();
    if (t < DETS){
        int p = pos[t];
        int gidx = s_gid[p];
        float4 b = g_box[img*NCAND + gidx];
        float* ob = out + (img*DETS + t)*4;
        ob[0] = b.x; ob[1] = b.y; ob[2] = b.z; ob[3] = b.w;
        out[BATCH*DETS*4 + img*DETS + t] = (t < cntF) ? s_sc[p] : -1.0f;
        out[BATCH*DETS*5 + img*DETS + t] = (float)g_label[img*NCAND + gidx];
    }
}

// -------- host: PDL launches --------
static inline void launch_pdl(const void* func, dim3 grid, dim3 block, size_t smem,
                              void** args, bool pdl){
    cudaLaunchConfig_t cfg = {};
    cfg.gridDim = grid; cfg.blockDim = block; cfg.dynamicSmemBytes = smem;
    cudaLaunchAttribute attr[1];
    attr[0].id = cudaLaunchAttributeProgrammaticStreamSerialization;
    attr[0].val.programmaticStreamSerializationAllowed = 1;
    cfg.attrs = attr;
    cfg.numAttrs = pdl ? 1 : 0;
    cudaLaunchKernelExC(&cfg, func, args);
}

extern "C" void kernel_launch(void* const* d_in, const int* in_sizes, int n_in,
                              void* d_out, int out_size){
    const float *cls[3], *reg[3], *ctr[3], *anc[3];
    if (in_sizes[1] == 655360){
        for (int i = 0; i < 3; i++){
            cls[i] = (const float*)d_in[i];
            reg[i] = (const float*)d_in[3 + i];
            ctr[i] = (const float*)d_in[6 + i];
            anc[i] = (const float*)d_in[9 + i];
        }
    } else {
        for (int i = 0; i < 3; i++){
            cls[i] = (const float*)d_in[4*i + 0];
            reg[i] = (const float*)d_in[4*i + 1];
            ctr[i] = (const float*)d_in[4*i + 2];
            anc[i] = (const float*)d_in[4*i + 3];
        }
    }
    float* out = (float*)d_out;

    cudaFuncSetAttribute(k_merge_nms, cudaFuncAttributeMaxDynamicSharedMemorySize, SMEM_NMS);

    int blocks = TOT / (STHREADS*EPT2);          // 840

    void* aScore[6] = { &cls[0],&cls[1],&cls[2], &ctr[0],&ctr[1],&ctr[2] };
    void* aLvl[12]  = { &cls[0],&cls[1],&cls[2], &ctr[0],&ctr[1],&ctr[2],
                        &reg[0],&reg[1],&reg[2], &anc[0],&anc[1],&anc[2] };
    void* aNms[1]   = { &out };

    launch_pdl((const void*)k_score,     dim3(blocks), dim3(STHREADS), 0, aScore, false);
    launch_pdl((const void*)k_levelsort, dim3(BATCH*NLEV), dim3(1024), 0, aLvl, true);
    launch_pdl((const void*)k_merge_nms, dim3(BATCH), dim3(NMT), SMEM_NMS, aNms, true);
}

// round 14
// speedup vs baseline: 1.1215x; 1.1215x over previous
#include <cuda_runtime.h>
#include <cstdint>

#define BATCH   8
#define NLEV    3
#define NCLS    80
#define TOPK    1000
#define NCAND   3000
#define DETS    100
#define CAPC    32768
#define NBINS   16384
#define IMGSZ   2048.0f
#define SCORE_TH 0.2f
#define NMS_TH   0.6f
#define BIN_SCALE 9216.0f
#define G_HI    (1.0f + (float)NBINS/BIN_SCALE)
#define EPT     16
#define SENT    0x7FFFFFFF

#define HW0 4096
#define HW1 1024
#define HW2 256
#define E0  (HW0*NCLS)
#define E1  (HW1*NCLS)
#define E2  (HW2*NCLS)
#define TOT (BATCH*(E0+E1+E2))

typedef unsigned long long ull;

// conservative per-level collection bins (s >= ~0.73 / 0.70 / 0.62)
static __constant__ int c_prebin[NLEV] = { 8078, 9592, 14760 };

// -------- scratch (zero-init; self-cleaned each replay) --------
static __device__ __align__(16) unsigned int g_hist[BATCH*NLEV*NBINS];
static __device__ unsigned int   g_cnt[BATCH*NLEV];
static __device__ ull            g_cand[BATCH*NLEV*CAPC];
static __device__ unsigned short g_binv[BATCH*NLEV*CAPC];
static __device__ float   g_score[BATCH*NCAND];
static __device__ int     g_label[BATCH*NCAND];
static __device__ float4  g_box[BATCH*NCAND];

__device__ __forceinline__ float sigm(float x){ return 1.0f/(1.0f+expf(-x)); }
__device__ __forceinline__ unsigned int fkey(float f){
    unsigned int u = __float_as_uint(f);
    return (u & 0x80000000u) ? ~u : (u | 0x80000000u);
}
__device__ __forceinline__ float keyToFloat(unsigned int k){
    unsigned int u = (k & 0x80000000u) ? (k & 0x7FFFFFFFu) : ~k;
    return __uint_as_float(u);
}
__device__ __forceinline__ int binOf(float g){
    return (int)(fmaxf(g - 1.0f, 0.0f) * BIN_SCALE);
}
__device__ __forceinline__ ull umin64(ull a, ull b){ return a < b ? a : b; }
__device__ __forceinline__ ull umax64(ull a, ull b){ return a > b ? a : b; }

struct Seg { int img, lvl, e, HW, E; };
__device__ __forceinline__ Seg decompose(int gid){
    Seg s;
    if (gid < BATCH*E0){ s.lvl=0; s.img=gid/E0; s.e=gid%E0; s.HW=HW0; s.E=E0; return s; }
    gid -= BATCH*E0;
    if (gid < BATCH*E1){ s.lvl=1; s.img=gid/E1; s.e=gid%E1; s.HW=HW1; s.E=E1; return s; }
    gid -= BATCH*E1;
    s.lvl=2; s.img=gid/E2; s.e=gid%E2; s.HW=HW2; s.E=E2; return s;
}

// ======== K1: scan; histogram/collect ONLY for bin <= prebin (~5% of elems) ========
#define SBUF 1024
__global__ void k_score(const float* __restrict__ cls0,const float* __restrict__ cls1,const float* __restrict__ cls2,
                        const float* __restrict__ ctr0,const float* __restrict__ ctr1,const float* __restrict__ ctr2){
    __shared__ ull            sbuf[SBUF];
    __shared__ unsigned short sbin[SBUF];
    __shared__ int sN, sBase;
    int tid = threadIdx.x;
    if (tid == 0) sN = 0;
    __syncthreads();
    int gid = (blockIdx.x*blockDim.x + tid)*EPT;
    Seg S = decompose(gid);              // one block = 4096 contiguous elems, single IL
    const float* cls = (S.lvl==0)?cls0:(S.lvl==1)?cls1:cls2;
    const float* ctr = (S.lvl==0)?ctr0:(S.lvl==1)?ctr1:ctr2;
    int IL = S.img*NLEV + S.lvl;
    size_t ILc = (size_t)IL*CAPC;
    int prebin = c_prebin[S.lvl];
    const float4* cp = reinterpret_cast<const float4*>(&cls[S.img*S.E + S.e]);
    float4 c0 = cp[0], c1 = cp[1], c2 = cp[2], c3 = cp[3];
    int a = S.e / NCLS;
    float tval = ctr[S.img*S.HW + a];
    float K = 1.0f + __expf(-tval);
    // conservative prefilter for bin <= prebin
    float gpre = 1.0f + (float)(prebin+1)/BIN_SCALE;
    float q = __fdividef(gpre, K);
    float Tc = (q <= 1.0f) ? 3.0e38f : (-__logf(q - 1.0f) - 1e-3f);
    float cv[EPT] = {c0.x,c0.y,c0.z,c0.w, c1.x,c1.y,c1.z,c1.w,
                     c2.x,c2.y,c2.z,c2.w, c3.x,c3.y,c3.z,c3.w};
    unsigned int* H = &g_hist[IL*NBINS];
    int lane = tid & 31;

    // phase 1: compare-only hot loop; exact bin + histogram on rare hits
    unsigned hitmask = 0;
    #pragma unroll
    for (int i = 0; i < EPT; i++){
        if (cv[i] > Tc){
            float g = fmaf(__expf(-cv[i]), K, K);   // exact same bin formula everywhere
            int b = binOf(g);
            if (b <= prebin){
                atomicAdd(&H[b], 1u);
                hitmask |= (1u << i);
            }
        }
    }

    // one warp scan for write positions
    int nloc = __popc(hitmask);
    unsigned incs = (unsigned)nloc;
    #pragma unroll
    for (int o = 1; o < 32; o <<= 1){
        unsigned v = __shfl_up_sync(0xFFFFFFFFu, incs, o);
        if (lane >= o) incs += v;
    }
    int wtot = __shfl_sync(0xFFFFFFFFu, (int)incs, 31);
    int wbase = 0;
    if (wtot){
        if (lane == 31) wbase = atomicAdd(&sN, wtot);
        wbase = __shfl_sync(0xFFFFFFFFu, wbase, 31);
    }
    int p = wbase + (int)incs - nloc;

    // phase 2: rare writes (static-index recompute)
    if (hitmask){
        #pragma unroll
        for (int i = 0; i < EPT; i++){
            if (hitmask & (1u << i)){
                float g = fmaf(__expf(-cv[i]), K, K);
                int b = binOf(g);
                float sex = sqrtf(sigm(cv[i]) * sigm(tval));   // exact reference score
                ull word = ~(((ull)fkey(sex) << 32) | (unsigned)(0xFFFFFFFFu - (unsigned)(S.e + i)));
                if (p < SBUF){ sbuf[p] = word; sbin[p] = (unsigned short)b; }
                else {
                    unsigned gp2 = atomicAdd(&g_cnt[IL], 1u);    // rare spill
                    if (gp2 < CAPC){ g_cand[ILc + gp2] = word; g_binv[ILc + gp2] = (unsigned short)b; }
                }
                p++;
            }
        }
    }
    __syncthreads();
    int n = min(sN, SBUF);
    if (tid == 0) sBase = (int)atomicAdd(&g_cnt[IL], (unsigned)n);
    __syncthreads();
    int base = sBase;
    for (int i = tid; i < n; i += blockDim.x){
        int gp2 = base + i;
        if (gp2 < CAPC){ g_cand[ILc + gp2] = sbuf[i]; g_binv[ILc + gp2] = sbin[i]; }
    }
}

// decode + clip + store one candidate
__device__ __forceinline__ void emit_cand(int img,int lvl,int r,int e,float score,
                                          const float* reg,const float* anc,int HW){
    int a = e / NCLS, lab = e % NCLS;
    float4 A = reinterpret_cast<const float4*>(anc)[a];
    float4 R = reinterpret_cast<const float4*>(reg)[img*HW + a];
    float cx = 0.5f*(A.x + A.z), cy = 0.5f*(A.y + A.w);
    float w = A.z - A.x, h = A.w - A.y;
    float x0 = fminf(fmaxf(cx - R.x*w, 0.0f), IMGSZ);
    float y0 = fminf(fmaxf(cy - R.y*h, 0.0f), IMGSZ);
    float x1 = fminf(fmaxf(cx + R.z*w, 0.0f), IMGSZ);
    float y1 = fminf(fmaxf(cy + R.w*h, 0.0f), IMGSZ);
    int g = img*NCAND + lvl*TOPK + r;
    g_score[g] = score;
    g_label[g] = lab;
    g_box[g]   = make_float4(x0,y0,x1,y1);
}

__device__ __forceinline__ void reg_substeps(ull &v0, ull &v1, int k, int jhi, int t){
    bool up = (((2*t) & k) == 0);
    for (int j = jhi; j >= 2; j >>= 1){
        int d = j >> 1;
        ull p0 = __shfl_xor_sync(0xFFFFFFFFu, v0, d);
        ull p1 = __shfl_xor_sync(0xFFFFFFFFu, v1, d);
        bool keepmin = (((t & d) == 0) == up);
        v0 = keepmin ? umin64(v0,p0) : umax64(v0,p0);
        v1 = keepmin ? umin64(v1,p1) : umax64(v1,p1);
    }
    ull a = umin64(v0,v1), b = umax64(v0,v1);
    v0 = up ? a : b;
    v1 = up ? b : a;
}

// parallel histogram scan + clean; writes bstar (or SENT) into *s_bstar.
__device__ __forceinline__ void hist_scan_clean(unsigned int* h, unsigned* wsum,
                                                volatile int* s_bstar,
                                                int t, int lane, int wid){
    uint4* hv = reinterpret_cast<uint4*>(h + t*16);
    uint4 a0 = hv[0], a1 = hv[1], a2 = hv[2], a3 = hv[3];
    unsigned vals[16] = {a0.x,a0.y,a0.z,a0.w, a1.x,a1.y,a1.z,a1.w,
                         a2.x,a2.y,a2.z,a2.w, a3.x,a3.y,a3.z,a3.w};
    unsigned s = 0;
    #pragma unroll
    for (int i = 0; i < 16; i++) s += vals[i];
    unsigned inc = s;
    #pragma unroll
    for (int o = 1; o < 32; o <<= 1){
        unsigned v = __shfl_up_sync(0xFFFFFFFFu, inc, o);
        if (lane >= o) inc += v;
    }
    if (lane == 31) wsum[wid] = inc;
    __syncthreads();
    if (wid == 0){
        unsigned winc = wsum[lane];
        #pragma unroll
        for (int o = 1; o < 32; o <<= 1){
            unsigned v = __shfl_up_sync(0xFFFFFFFFu, winc, o);
            if (lane >= o) winc += v;
        }
        wsum[lane] = winc;
    }
    __syncthreads();
    unsigned below = ((wid == 0) ? 0u : wsum[wid-1]) + (inc - s);
    if (below < TOPK && below + s >= TOPK){
        unsigned cum = below;
        #pragma unroll
        for (int i = 0; i < 16; i++){
            cum += vals[i];
            if (cum >= TOPK){ *s_bstar = t*16 + i; break; }
        }
    }
    uint4 z4 = make_uint4(0,0,0,0);
    hv[0] = z4; hv[1] = z4; hv[2] = z4; hv[3] = z4;
    __syncthreads();
}

// ======== K2: cutoff + compact (or full-rescan fallback) + sort + emit ========
__global__ void __launch_bounds__(1024, 1)
k_levelsort(const float* __restrict__ cls0,const float* __restrict__ cls1,const float* __restrict__ cls2,
            const float* __restrict__ ctr0,const float* __restrict__ ctr1,const float* __restrict__ ctr2,
            const float* __restrict__ reg0,const float* __restrict__ reg1,const float* __restrict__ reg2,
            const float* __restrict__ anc0,const float* __restrict__ anc1,const float* __restrict__ anc2){
    __shared__ ull sh[4096];
    __shared__ unsigned wsum[32];
    __shared__ int s_bstar, s_cnt, s_in;
    cudaGridDependencySynchronize();
    int img = blockIdx.x / NLEV, lvl = blockIdx.x % NLEV;
    int IL = img*NLEV + lvl;
    int t = threadIdx.x, lane = t & 31, wid = t >> 5;
    unsigned int* h = &g_hist[IL*NBINS];

    if (t == 0){
        s_bstar = SENT;
        s_in  = (int)g_cnt[IL];
        g_cnt[IL] = 0u;
        s_cnt = 0;
    }
    __syncthreads();
    hist_scan_clean(h, wsum, &s_bstar, t, lane, wid);
    int bstar = s_bstar;
    int cnt   = s_in;

    const float *reg, *anc, *cls, *ctr; int HW, E;
    if (lvl == 0){ reg=reg0; anc=anc0; cls=cls0; ctr=ctr0; HW=HW0; E=E0; }
    else if (lvl == 1){ reg=reg1; anc=anc1; cls=cls1; ctr=ctr1; HW=HW1; E=E1; }
    else { reg=reg2; anc=anc2; cls=cls2; ctr=ctr2; HW=HW2; E=E2; }

    bool fast = (bstar != SENT) && (bstar <= c_prebin[lvl]) && (cnt <= CAPC);
    size_t ILc = (size_t)IL*CAPC;
    if (fast){
        int n = cnt;
        int nPad = (n + 1023) & ~1023;
        for (int i = t; i < nPad; i += 1024){
            bool keep = (i < n) && (g_binv[ILc + i] <= (unsigned short)bstar);
            ull w = keep ? g_cand[ILc + i] : 0;
            unsigned ball = __ballot_sync(0xFFFFFFFFu, keep);
            int nw = __popc(ball);
            if (nw){
                int bpos = 0;
                if (lane == 0) bpos = atomicAdd(&s_cnt, nw);
                bpos = __shfl_sync(0xFFFFFFFFu, bpos, 0);
                if (keep){
                    int p = bpos + __popc(ball & ((1u << lane) - 1u));
                    if (p < 4096) sh[p] = w;
                }
            }
        }
    } else {
        // ---- fallback (statistically dead, fully correct) ----
        int groups = E / EPT;
        for (int G = t; G < groups; G += 1024){
            int e0 = G*EPT;
            int a = G / 5;                           // 80 = 5*16
            float tval = ctr[img*HW + a];
            float K = 1.0f + __expf(-tval);
            float q2 = __fdividef(G_HI, K);
            float TcF = (q2 <= 1.0f) ? 3.0e38f : (-__logf(q2 - 1.0f) - 1e-3f);
            const float4* cp = reinterpret_cast<const float4*>(&cls[img*E + e0]);
            float4 c0 = cp[0], c1 = cp[1], c2 = cp[2], c3 = cp[3];
            float cv[EPT] = {c0.x,c0.y,c0.z,c0.w, c1.x,c1.y,c1.z,c1.w,
                             c2.x,c2.y,c2.z,c2.w, c3.x,c3.y,c3.z,c3.w};
            #pragma unroll
            for (int i = 0; i < EPT; i++){
                if (cv[i] > TcF){
                    float g = fmaf(__expf(-cv[i]), K, K);
                    int b = binOf(g);
                    if (b < NBINS) atomicAdd(&h[b], 1u);
                }
            }
        }
        __syncthreads();
        if (t == 0) s_bstar = SENT;
        __syncthreads();
        hist_scan_clean(h, wsum, &s_bstar, t, lane, wid);
        bstar = s_bstar;
        for (int G = t; G < groups; G += 1024){
            int e0 = G*EPT;
            int a = G / 5;
            float tval = ctr[img*HW + a];
            float K = 1.0f + __expf(-tval);
            float thrv;
            if (bstar == SENT) thrv = -3.0e38f;
            else {
                float Gm = (1.0f + (float)(bstar+1)/BIN_SCALE) * 1.003f;
                float qr = Gm / K;
                thrv = (qr <= 1.0000012f) ? 3.0e38f : (-logf(qr - 1.0f) - 0.003f);
            }
            const float4* cp = reinterpret_cast<const float4*>(&cls[img*E + e0]);
            float4 c0 = cp[0], c1 = cp[1], c2 = cp[2], c3 = cp[3];
            float cv[EPT] = {c0.x,c0.y,c0.z,c0.w, c1.x,c1.y,c1.z,c1.w,
                             c2.x,c2.y,c2.z,c2.w, c3.x,c3.y,c3.z,c3.w};
            #pragma unroll
            for (int i = 0; i < EPT; i++){
                if (cv[i] > thrv){
                    bool mem = true;
                    if (bstar != SENT){
                        float g = fmaf(__expf(-cv[i]), K, K);
                        mem = (binOf(g) <= bstar);
                    }
                    if (mem){
                        float sex = sqrtf(sigm(cv[i]) * sigm(tval));
                        if (bstar != SENT || sex > SCORE_TH){
                            ull w = ~(((ull)fkey(sex) << 32) | (unsigned)(0xFFFFFFFFu - (unsigned)(e0 + i)));
                            int p = atomicAdd(&s_cnt, 1);
                            if (p < 4096) sh[p] = w;
                        }
                    }
                }
            }
        }
    }
    __syncthreads();
    int C = min(s_cnt, 4096);
    int N = (C <= 1024) ? 1024 : (C <= 2048 ? 2048 : 4096);
    for (int i = C + t; i < N; i += 1024) sh[i] = ~0ULL;
    __syncthreads();

    // ---- hybrid shuffle/smem bitonic sort of N ----
    if (N <= 2048){
        int half = N >> 1;
        ull v0 = 0, v1 = 0;
        if (t < half){
            v0 = sh[2*t]; v1 = sh[2*t+1];
            #pragma unroll
            for (int k = 2; k <= 64; k <<= 1)
                reg_substeps(v0, v1, k, (k>>1) >= 2 ? (k>>1) : 0, t);
            sh[2*t] = v0; sh[2*t+1] = v1;
        }
        __syncthreads();
        for (int k = 128; k <= N; k <<= 1){
            for (int j = k>>1; j >= 64; j >>= 1){
                for (int i = t; i < N; i += 1024){
                    int l = i ^ j;
                    if (l > i){
                        ull a = sh[i], b = sh[l];
                        bool up = ((i & k) == 0);
                        if ((a > b) == up){ sh[i] = b; sh[l] = a; }
                    }
                }
                __syncthreads();
            }
            if (t < half){
                v0 = sh[2*t]; v1 = sh[2*t+1];
                reg_substeps(v0, v1, k, 32, t);
                sh[2*t] = v0; sh[2*t+1] = v1;
            }
            __syncthreads();
        }
    } else {
        for (int k = 2; k <= N; k <<= 1)
            for (int j = k>>1; j > 0; j >>= 1){
                for (int i = t; i < N; i += 1024){
                    int l = i ^ j;
                    if (l > i){
                        ull a = sh[i], b = sh[l];
                        bool up = ((i & k) == 0);
                        if ((a > b) == up){ sh[i] = b; sh[l] = a; }
                    }
                }
                __syncthreads();
            }
    }

    int validK = min(C, TOPK);
    for (int r = t; r < validK; r += 1024){
        ull comb = ~sh[r];
        unsigned key = (unsigned)(comb >> 32);
        int e = (int)(0xFFFFFFFFu - (unsigned)comb);
        emit_cand(img, lvl, r, e, keyToFloat(key), reg, anc, HW);
    }
    if (validK < TOPK && t < 32){
        int nfill = TOPK - validK;
        int cum = 0;
        for (int b = 0; b < E && cum < nfill; b += 32){
            int e = b + t;
            bool fail = false;
            if (e < E){
                float sc2 = sqrtf(sigm(cls[(long long)img*E + e]) * sigm(ctr[img*HW + e/NCLS]));
                fail = !(sc2 > SCORE_TH);
            }
            unsigned bal = __ballot_sync(0xFFFFFFFFu, fail);
            int pre = __popc(bal & ((1u << t) - 1u));
            if (fail && cum + pre < nfill)
                emit_cand(img, lvl, validK + cum + pre, e, -1.0f, reg, anc, HW);
            cum += __popc(bal);
        }
    }
}

// ======== K3: binary-search merge of 3 sorted lists + warp NMS + output ========
#define NMT 1024
#define NPT 3
#define OFF_KEY  0
#define OFF_SC   12000
#define OFF_AR   24000
#define OFF_GID  36000
#define OFF_OB   48000
#define OFF_KP   96000
#define OFF_POS  99000
#define OFF_CTL  99400
#define SMEM_NMS 99424

__global__ void __launch_bounds__(NMT, 1)
k_merge_nms(float* __restrict__ out){
    extern __shared__ char dyn[];
    unsigned int*   skey = (unsigned int*)(dyn + OFF_KEY);
    float*          s_sc = (float*)(dyn + OFF_SC);
    float*          s_ar = (float*)(dyn + OFF_AR);
    int*            s_gid= (int*)(dyn + OFF_GID);
    float4*         s_ob = (float4*)(dyn + OFF_OB);
    unsigned char*  kp   = (unsigned char*)(dyn + OFF_KP);
    int*            pos  = (int*)(dyn + OFF_POS);
    int*            ctl  = (int*)(dyn + OFF_CTL);
    cudaGridDependencySynchronize();
    int img = blockIdx.x, t = threadIdx.x;
    int lane = t & 31;

    #pragma unroll
    for (int k = 0; k < NPT; k++){
        int i = t + k*NMT;
        if (i < NCAND){
            skey[i] = fkey(g_score[img*NCAND + i]);
            kp[i] = 0;
        }
    }
    __syncthreads();

    #pragma unroll
    for (int k = 0; k < NPT; k++){
        int i = t + k*NMT;
        if (i < NCAND){
            int L = i / TOPK, r = i - L*TOPK;
            unsigned key = skey[i];
            int m = r;
            #pragma unroll
            for (int M = 0; M < NLEV; M++){
                if (M == L) continue;
                const unsigned* a2 = &skey[M*TOPK];
                int lo = 0, hi = TOPK;
                if (M < L){
                    while (lo < hi){ int mid = (lo+hi)>>1; if (a2[mid] >= key) lo = mid+1; else hi = mid; }
                } else {
                    while (lo < hi){ int mid = (lo+hi)>>1; if (a2[mid] >  key) lo = mid+1; else hi = mid; }
                }
                m += lo;
            }
            s_sc[m]  = keyToFloat(key);
            s_gid[m] = i;
            float4 b = g_box[img*NCAND + i];
            float off = (IMGSZ + 1.0f) * (float)g_label[img*NCAND + i];
            float4 ob = make_float4(b.x+off, b.y+off, b.z+off, b.w+off);
            s_ob[m] = ob;
            s_ar[m] = (ob.z - ob.x) * (ob.w - ob.y);
        }
    }
    __syncthreads();

    if (t < 32){
        float kx0[4], ky0[4], kx1[4], ky1[4], kar[4];
        int cnt = 0;
        float  sc_n = s_sc[0];
        float4 bx_n = s_ob[0];
        float  ax_n = s_ar[0];
        for (int ii = 0; ii < NCAND; ii++){
            float sc = sc_n; float4 bx = bx_n; float ax = ax_n;
            if (ii + 1 < NCAND){ sc_n = s_sc[ii+1]; bx_n = s_ob[ii+1]; ax_n = s_ar[ii+1]; }
            if (!(sc > 0.0f)) break;
            bool sup = false;
            #pragma unroll
            for (int s2 = 0; s2 < 4; s2++){
                if (s2*32 + lane < cnt){
                    float xx0 = fmaxf(bx.x, kx0[s2]), yy0 = fmaxf(bx.y, ky0[s2]);
                    float xx1 = fminf(bx.z, kx1[s2]), yy1 = fminf(bx.w, ky1[s2]);
                    float iw = xx1 - xx0, ih = yy1 - yy0;
                    if (iw > 0.0f && ih > 0.0f){
                        float inter = iw * ih;
                        if (inter / (ax + kar[s2] - inter) > NMS_TH) sup = true;
                    }
                }
            }
            if (__any_sync(0xFFFFFFFFu, sup)) continue;
            if (lane == 0){ pos[cnt] = ii; kp[ii] = 1; }
            if (lane == (cnt & 31)){
                int sl = cnt >> 5;
                if      (sl == 0){ kx0[0]=bx.x; ky0[0]=bx.y; kx1[0]=bx.z; ky1[0]=bx.w; kar[0]=ax; }
                else if (sl == 1){ kx0[1]=bx.x; ky0[1]=bx.y; kx1[1]=bx.z; ky1[1]=bx.w; kar[1]=ax; }
                else if (sl == 2){ kx0[2]=bx.x; ky0[2]=bx.y; kx1[2]=bx.z; ky1[2]=bx.w; kar[2]=ax; }
                else             { kx0[3]=bx.x; ky0[3]=bx.y; kx1[3]=bx.z; ky1[3]=bx.w; kar[3]=ax; }
            }
            cnt++;
            if (cnt >= DETS) break;
        }
        if (lane == 0) ctl[0] = cnt;
    }
    __syncthreads();
    int cntF = ctl[0];
    if (t == 0 && cntF < DETS){
        int fill = cntF;
        for (int p = 0; p < NCAND && fill < DETS; p++)
            if (!kp[p]) pos[fill++] = p;
    }
    __syncthreads();
    if (t < DETS){
        int p = pos[t];
        int gidx = s_gid[p];
        float4 b = g_box[img*NCAND + gidx];
        float* ob = out + (img*DETS + t)*4;
        ob[0] = b.x; ob[1] = b.y; ob[2] = b.z; ob[3] = b.w;
        out[BATCH*DETS*4 + img*DETS + t] = (t < cntF) ? s_sc[p] : -1.0f;
        out[BATCH*DETS*5 + img*DETS + t] = (float)g_label[img*NCAND + gidx];
    }
}

// -------- host: PDL launches --------
static inline void launch_pdl(const void* func, dim3 grid, dim3 block, size_t smem,
                              void** args, bool pdl){
    cudaLaunchConfig_t cfg = {};
    cfg.gridDim = grid; cfg.blockDim = block; cfg.dynamicSmemBytes = smem;
    cudaLaunchAttribute attr[1];
    attr[0].id = cudaLaunchAttributeProgrammaticStreamSerialization;
    attr[0].val.programmaticStreamSerializationAllowed = 1;
    cfg.attrs = attr;
    cfg.numAttrs = pdl ? 1 : 0;
    cudaLaunchKernelExC(&cfg, func, args);
}

extern "C" void kernel_launch(void* const* d_in, const int* in_sizes, int n_in,
                              void* d_out, int out_size){
    const float *cls[3], *reg[3], *ctr[3], *anc[3];
    if (in_sizes[1] == 655360){
        for (int i = 0; i < 3; i++){
            cls[i] = (const float*)d_in[i];
            reg[i] = (const float*)d_in[3 + i];
            ctr[i] = (const float*)d_in[6 + i];
            anc[i] = (const float*)d_in[9 + i];
        }
    } else {
        for (int i = 0; i < 3; i++){
            cls[i] = (const float*)d_in[4*i + 0];
            reg[i] = (const float*)d_in[4*i + 1];
            ctr[i] = (const float*)d_in[4*i + 2];
            anc[i] = (const float*)d_in[4*i + 3];
        }
    }
    float* out = (float*)d_out;

    cudaFuncSetAttribute(k_merge_nms, cudaFuncAttributeMaxDynamicSharedMemorySize, SMEM_NMS);

    int groups = TOT/EPT;
    int blocks = (groups + 255)/256;

    void* aScore[6] = { &cls[0],&cls[1],&cls[2], &ctr[0],&ctr[1],&ctr[2] };
    void* aLvl[12]  = { &cls[0],&cls[1],&cls[2], &ctr[0],&ctr[1],&ctr[2],
                        &reg[0],&reg[1],&reg[2], &anc[0],&anc[1],&anc[2] };
    void* aNms[1]   = { &out };

    launch_pdl((const void*)k_score,     dim3(blocks), dim3(256), 0, aScore, false);
    launch_pdl((const void*)k_levelsort, dim3(BATCH*NLEV), dim3(1024), 0, aLvl, true);
    launch_pdl((const void*)k_merge_nms, dim3(BATCH), dim3(NMT), SMEM_NMS, aNms, true);
}

// round 15
// speedup vs baseline: 1.1707x; 1.0438x over previous
#include <cuda_runtime.h>
#include <cstdint>

#define BATCH   8
#define NLEV    3
#define NCLS    80
#define TOPK    1000
#define NCAND   3000
#define DETS    100
#define CAPC    32768
#define NBINS   16384
#define IMGSZ   2048.0f
#define SCORE_TH 0.2f
#define NMS_TH   0.6f
#define BIN_SCALE 9216.0f
#define G_HI    (1.0f + (float)NBINS/BIN_SCALE)
#define EPT     16           /* fallback path granularity (k_levelsort) */
#define EPS     8            /* k_score elements per thread */
#define SENT    0x7FFFFFFF

#define HW0 4096
#define HW1 1024
#define HW2 256
#define E0  (HW0*NCLS)
#define E1  (HW1*NCLS)
#define E2  (HW2*NCLS)
#define TOT (BATCH*(E0+E1+E2))

typedef unsigned long long ull;

// conservative per-level collection bins (s >= ~0.73 / 0.70 / 0.62)
static __constant__ int c_prebin[NLEV] = { 8078, 9592, 14760 };

// -------- scratch (zero-init; self-cleaned each replay) --------
static __device__ __align__(16) unsigned int g_hist[BATCH*NLEV*NBINS];
static __device__ unsigned int   g_cnt[BATCH*NLEV];
static __device__ ull            g_cand[BATCH*NLEV*CAPC];
static __device__ unsigned short g_binv[BATCH*NLEV*CAPC];
static __device__ float   g_score[BATCH*NCAND];
static __device__ int     g_label[BATCH*NCAND];
static __device__ float4  g_box[BATCH*NCAND];

__device__ __forceinline__ float sigm(float x){ return 1.0f/(1.0f+expf(-x)); }
__device__ __forceinline__ unsigned int fkey(float f){
    unsigned int u = __float_as_uint(f);
    return (u & 0x80000000u) ? ~u : (u | 0x80000000u);
}
__device__ __forceinline__ float keyToFloat(unsigned int k){
    unsigned int u = (k & 0x80000000u) ? (k & 0x7FFFFFFFu) : ~k;
    return __uint_as_float(u);
}
__device__ __forceinline__ int binOf(float g){
    return (int)(fmaxf(g - 1.0f, 0.0f) * BIN_SCALE);
}
__device__ __forceinline__ ull umin64(ull a, ull b){ return a < b ? a : b; }
__device__ __forceinline__ ull umax64(ull a, ull b){ return a > b ? a : b; }

struct Seg { int img, lvl, e, HW, E; };
__device__ __forceinline__ Seg decompose(int gid){
    Seg s;
    if (gid < BATCH*E0){ s.lvl=0; s.img=gid/E0; s.e=gid%E0; s.HW=HW0; s.E=E0; return s; }
    gid -= BATCH*E0;
    if (gid < BATCH*E1){ s.lvl=1; s.img=gid/E1; s.e=gid%E1; s.HW=HW1; s.E=E1; return s; }
    gid -= BATCH*E1;
    s.lvl=2; s.img=gid/E2; s.e=gid%E2; s.HW=HW2; s.E=E2; return s;
}

// ======== K1: 8 elems/thread (max load parallelism); collect bin <= prebin ========
#define SBUF 1024
__global__ void k_score(const float* __restrict__ cls0,const float* __restrict__ cls1,const float* __restrict__ cls2,
                        const float* __restrict__ ctr0,const float* __restrict__ ctr1,const float* __restrict__ ctr2){
    __shared__ ull            sbuf[SBUF];
    __shared__ unsigned short sbin[SBUF];
    __shared__ int sN, sBase;
    int tid = threadIdx.x;
    if (tid == 0) sN = 0;
    __syncthreads();
    int gid = (blockIdx.x*blockDim.x + tid)*EPS;
    Seg S = decompose(gid);              // one block = 2048 contiguous elems, single IL
    const float* cls = (S.lvl==0)?cls0:(S.lvl==1)?cls1:cls2;
    const float* ctr = (S.lvl==0)?ctr0:(S.lvl==1)?ctr1:ctr2;
    int IL = S.img*NLEV + S.lvl;
    size_t ILc = (size_t)IL*CAPC;
    int prebin = c_prebin[S.lvl];
    const float4* cp = reinterpret_cast<const float4*>(&cls[S.img*S.E + S.e]);
    float4 c0 = cp[0], c1 = cp[1];
    int a = S.e / NCLS;                  // 8 | 80 -> group never crosses anchor
    float tval = ctr[S.img*S.HW + a];
    float K = 1.0f + __expf(-tval);
    float gpre = 1.0f + (float)(prebin+1)/BIN_SCALE;
    float q = __fdividef(gpre, K);
    float Tc = (q <= 1.0f) ? 3.0e38f : (-__logf(q - 1.0f) - 1e-3f);
    float cv[EPS] = {c0.x,c0.y,c0.z,c0.w, c1.x,c1.y,c1.z,c1.w};
    unsigned int* H = &g_hist[IL*NBINS];
    int lane = tid & 31;

    unsigned hitmask = 0;
    #pragma unroll
    for (int i = 0; i < EPS; i++){
        if (cv[i] > Tc){
            float g = fmaf(__expf(-cv[i]), K, K);   // exact same bin formula everywhere
            int b = binOf(g);
            if (b <= prebin){
                atomicAdd(&H[b], 1u);
                hitmask |= (1u << i);
            }
        }
    }

    // one warp scan for write positions
    int nloc = __popc(hitmask);
    unsigned incs = (unsigned)nloc;
    #pragma unroll
    for (int o = 1; o < 32; o <<= 1){
        unsigned v = __shfl_up_sync(0xFFFFFFFFu, incs, o);
        if (lane >= o) incs += v;
    }
    int wtot = __shfl_sync(0xFFFFFFFFu, (int)incs, 31);
    int wbase = 0;
    if (wtot){
        if (lane == 31) wbase = atomicAdd(&sN, wtot);
        wbase = __shfl_sync(0xFFFFFFFFu, wbase, 31);
    }
    int p = wbase + (int)incs - nloc;

    if (hitmask){
        #pragma unroll
        for (int i = 0; i < EPS; i++){
            if (hitmask & (1u << i)){
                float g = fmaf(__expf(-cv[i]), K, K);
                int b = binOf(g);
                float sex = sqrtf(sigm(cv[i]) * sigm(tval));   // exact reference score
                ull word = ~(((ull)fkey(sex) << 32) | (unsigned)(0xFFFFFFFFu - (unsigned)(S.e + i)));
                if (p < SBUF){ sbuf[p] = word; sbin[p] = (unsigned short)b; }
                else {
                    unsigned gp2 = atomicAdd(&g_cnt[IL], 1u);    // rare spill
                    if (gp2 < CAPC){ g_cand[ILc + gp2] = word; g_binv[ILc + gp2] = (unsigned short)b; }
                }
                p++;
            }
        }
    }
    __syncthreads();
    int n = min(sN, SBUF);
    if (tid == 0) sBase = (int)atomicAdd(&g_cnt[IL], (unsigned)n);
    __syncthreads();
    int base = sBase;
    for (int i = tid; i < n; i += blockDim.x){
        int gp2 = base + i;
        if (gp2 < CAPC){ g_cand[ILc + gp2] = sbuf[i]; g_binv[ILc + gp2] = sbin[i]; }
    }
}

// decode + clip + store one candidate
__device__ __forceinline__ void emit_cand(int img,int lvl,int r,int e,float score,
                                          const float* reg,const float* anc,int HW){
    int a = e / NCLS, lab = e % NCLS;
    float4 A = reinterpret_cast<const float4*>(anc)[a];
    float4 R = reinterpret_cast<const float4*>(reg)[img*HW + a];
    float cx = 0.5f*(A.x + A.z), cy = 0.5f*(A.y + A.w);
    float w = A.z - A.x, h = A.w - A.y;
    float x0 = fminf(fmaxf(cx - R.x*w, 0.0f), IMGSZ);
    float y0 = fminf(fmaxf(cy - R.y*h, 0.0f), IMGSZ);
    float x1 = fminf(fmaxf(cx + R.z*w, 0.0f), IMGSZ);
    float y1 = fminf(fmaxf(cy + R.w*h, 0.0f), IMGSZ);
    int g = img*NCAND + lvl*TOPK + r;
    g_score[g] = score;
    g_label[g] = lab;
    g_box[g]   = make_float4(x0,y0,x1,y1);
}

__device__ __forceinline__ void reg_substeps(ull &v0, ull &v1, int k, int jhi, int t){
    bool up = (((2*t) & k) == 0);
    for (int j = jhi; j >= 2; j >>= 1){
        int d = j >> 1;
        ull p0 = __shfl_xor_sync(0xFFFFFFFFu, v0, d);
        ull p1 = __shfl_xor_sync(0xFFFFFFFFu, v1, d);
        bool keepmin = (((t & d) == 0) == up);
        v0 = keepmin ? umin64(v0,p0) : umax64(v0,p0);
        v1 = keepmin ? umin64(v1,p1) : umax64(v1,p1);
    }
    ull a = umin64(v0,v1), b = umax64(v0,v1);
    v0 = up ? a : b;
    v1 = up ? b : a;
}

// parallel histogram scan + clean; writes bstar (or SENT) into *s_bstar.
__device__ __forceinline__ void hist_scan_clean(unsigned int* h, unsigned* wsum,
                                                volatile int* s_bstar,
                                                int t, int lane, int wid){
    uint4* hv = reinterpret_cast<uint4*>(h + t*16);
    uint4 a0 = hv[0], a1 = hv[1], a2 = hv[2], a3 = hv[3];
    unsigned vals[16] = {a0.x,a0.y,a0.z,a0.w, a1.x,a1.y,a1.z,a1.w,
                         a2.x,a2.y,a2.z,a2.w, a3.x,a3.y,a3.z,a3.w};
    unsigned s = 0;
    #pragma unroll
    for (int i = 0; i < 16; i++) s += vals[i];
    unsigned inc = s;
    #pragma unroll
    for (int o = 1; o < 32; o <<= 1){
        unsigned v = __shfl_up_sync(0xFFFFFFFFu, inc, o);
        if (lane >= o) inc += v;
    }
    if (lane == 31) wsum[wid] = inc;
    __syncthreads();
    if (wid == 0){
        unsigned winc = wsum[lane];
        #pragma unroll
        for (int o = 1; o < 32; o <<= 1){
            unsigned v = __shfl_up_sync(0xFFFFFFFFu, winc, o);
            if (lane >= o) winc += v;
        }
        wsum[lane] = winc;
    }
    __syncthreads();
    unsigned below = ((wid == 0) ? 0u : wsum[wid-1]) + (inc - s);
    if (below < TOPK && below + s >= TOPK){
        unsigned cum = below;
        #pragma unroll
        for (int i = 0; i < 16; i++){
            cum += vals[i];
            if (cum >= TOPK){ *s_bstar = t*16 + i; break; }
        }
    }
    uint4 z4 = make_uint4(0,0,0,0);
    hv[0] = z4; hv[1] = z4; hv[2] = z4; hv[3] = z4;
    __syncthreads();
}

// ======== K2: cutoff + compact (or full-rescan fallback) + sort + emit ========
__global__ void __launch_bounds__(1024, 1)
k_levelsort(const float* __restrict__ cls0,const float* __restrict__ cls1,const float* __restrict__ cls2,
            const float* __restrict__ ctr0,const float* __restrict__ ctr1,const float* __restrict__ ctr2,
            const float* __restrict__ reg0,const float* __restrict__ reg1,const float* __restrict__ reg2,
            const float* __restrict__ anc0,const float* __restrict__ anc1,const float* __restrict__ anc2){
    __shared__ ull sh[4096];
    __shared__ unsigned wsum[32];
    __shared__ int s_bstar, s_cnt, s_in;
    cudaGridDependencySynchronize();
    int img = blockIdx.x / NLEV, lvl = blockIdx.x % NLEV;
    int IL = img*NLEV + lvl;
    int t = threadIdx.x, lane = t & 31, wid = t >> 5;
    unsigned int* h = &g_hist[IL*NBINS];

    if (t == 0){
        s_bstar = SENT;
        s_in  = (int)g_cnt[IL];
        g_cnt[IL] = 0u;
        s_cnt = 0;
    }
    __syncthreads();
    hist_scan_clean(h, wsum, &s_bstar, t, lane, wid);
    int bstar = s_bstar;
    int cnt   = s_in;

    const float *reg, *anc, *cls, *ctr; int HW, E;
    if (lvl == 0){ reg=reg0; anc=anc0; cls=cls0; ctr=ctr0; HW=HW0; E=E0; }
    else if (lvl == 1){ reg=reg1; anc=anc1; cls=cls1; ctr=ctr1; HW=HW1; E=E1; }
    else { reg=reg2; anc=anc2; cls=cls2; ctr=ctr2; HW=HW2; E=E2; }

    bool fast = (bstar != SENT) && (bstar <= c_prebin[lvl]) && (cnt <= CAPC);
    size_t ILc = (size_t)IL*CAPC;
    if (fast){
        int n = cnt;
        int nPad = (n + 1023) & ~1023;
        for (int i = t; i < nPad; i += 1024){
            bool keep = (i < n) && (g_binv[ILc + i] <= (unsigned short)bstar);
            ull w = keep ? g_cand[ILc + i] : 0;
            unsigned ball = __ballot_sync(0xFFFFFFFFu, keep);
            int nw = __popc(ball);
            if (nw){
                int bpos = 0;
                if (lane == 0) bpos = atomicAdd(&s_cnt, nw);
                bpos = __shfl_sync(0xFFFFFFFFu, bpos, 0);
                if (keep){
                    int p = bpos + __popc(ball & ((1u << lane) - 1u));
                    if (p < 4096) sh[p] = w;
                }
            }
        }
    } else {
        // ---- fallback (statistically dead, fully correct) ----
        int groups = E / EPT;
        for (int G = t; G < groups; G += 1024){
            int e0 = G*EPT;
            int a = G / 5;                           // 80 = 5*16
            float tval = ctr[img*HW + a];
            float K = 1.0f + __expf(-tval);
            float q2 = __fdividef(G_HI, K);
            float TcF = (q2 <= 1.0f) ? 3.0e38f : (-__logf(q2 - 1.0f) - 1e-3f);
            const float4* cp = reinterpret_cast<const float4*>(&cls[img*E + e0]);
            float4 c0 = cp[0], c1 = cp[1], c2 = cp[2], c3 = cp[3];
            float cv[EPT] = {c0.x,c0.y,c0.z,c0.w, c1.x,c1.y,c1.z,c1.w,
                             c2.x,c2.y,c2.z,c2.w, c3.x,c3.y,c3.z,c3.w};
            #pragma unroll
            for (int i = 0; i < EPT; i++){
                if (cv[i] > TcF){
                    float g = fmaf(__expf(-cv[i]), K, K);
                    int b = binOf(g);
                    if (b < NBINS) atomicAdd(&h[b], 1u);
                }
            }
        }
        __syncthreads();
        if (t == 0) s_bstar = SENT;
        __syncthreads();
        hist_scan_clean(h, wsum, &s_bstar, t, lane, wid);
        bstar = s_bstar;
        for (int G = t; G < groups; G += 1024){
            int e0 = G*EPT;
            int a = G / 5;
            float tval = ctr[img*HW + a];
            float K = 1.0f + __expf(-tval);
            float thrv;
            if (bstar == SENT) thrv = -3.0e38f;
            else {
                float Gm = (1.0f + (float)(bstar+1)/BIN_SCALE) * 1.003f;
                float qr = Gm / K;
                thrv = (qr <= 1.0000012f) ? 3.0e38f : (-logf(qr - 1.0f) - 0.003f);
            }
            const float4* cp = reinterpret_cast<const float4*>(&cls[img*E + e0]);
            float4 c0 = cp[0], c1 = cp[1], c2 = cp[2], c3 = cp[3];
            float cv[EPT] = {c0.x,c0.y,c0.z,c0.w, c1.x,c1.y,c1.z,c1.w,
                             c2.x,c2.y,c2.z,c2.w, c3.x,c3.y,c3.z,c3.w};
            #pragma unroll
            for (int i = 0; i < EPT; i++){
                if (cv[i] > thrv){
                    bool mem = true;
                    if (bstar != SENT){
                        float g = fmaf(__expf(-cv[i]), K, K);
                        mem = (binOf(g) <= bstar);
                    }
                    if (mem){
                        float sex = sqrtf(sigm(cv[i]) * sigm(tval));
                        if (bstar != SENT || sex > SCORE_TH){
                            ull w = ~(((ull)fkey(sex) << 32) | (unsigned)(0xFFFFFFFFu - (unsigned)(e0 + i)));
                            int p = atomicAdd(&s_cnt, 1);
                            if (p < 4096) sh[p] = w;
                        }
                    }
                }
            }
        }
    }
    __syncthreads();
    int C = min(s_cnt, 4096);
    int N = (C <= 1024) ? 1024 : (C <= 2048 ? 2048 : 4096);
    for (int i = C + t; i < N; i += 1024) sh[i] = ~0ULL;
    __syncthreads();

    // ---- hybrid shuffle/smem bitonic sort of N ----
    if (N <= 2048){
        int half = N >> 1;
        ull v0 = 0, v1 = 0;
        if (t < half){
            v0 = sh[2*t]; v1 = sh[2*t+1];
            #pragma unroll
            for (int k = 2; k <= 64; k <<= 1)
                reg_substeps(v0, v1, k, (k>>1) >= 2 ? (k>>1) : 0, t);
            sh[2*t] = v0; sh[2*t+1] = v1;
        }
        __syncthreads();
        for (int k = 128; k <= N; k <<= 1){
            for (int j = k>>1; j >= 64; j >>= 1){
                for (int i = t; i < N; i += 1024){
                    int l = i ^ j;
                    if (l > i){
                        ull a = sh[i], b = sh[l];
                        bool up = ((i & k) == 0);
                        if ((a > b) == up){ sh[i] = b; sh[l] = a; }
                    }
                }
                __syncthreads();
            }
            if (t < half){
                v0 = sh[2*t]; v1 = sh[2*t+1];
                reg_substeps(v0, v1, k, 32, t);
                sh[2*t] = v0; sh[2*t+1] = v1;
            }
            __syncthreads();
        }
    } else {
        for (int k = 2; k <= N; k <<= 1)
            for (int j = k>>1; j > 0; j >>= 1){
                for (int i = t; i < N; i += 1024){
                    int l = i ^ j;
                    if (l > i){
                        ull a = sh[i], b = sh[l];
                        bool up = ((i & k) == 0);
                        if ((a > b) == up){ sh[i] = b; sh[l] = a; }
                    }
                }
                __syncthreads();
            }
    }

    int validK = min(C, TOPK);
    for (int r = t; r < validK; r += 1024){
        ull comb = ~sh[r];
        unsigned key = (unsigned)(comb >> 32);
        int e = (int)(0xFFFFFFFFu - (unsigned)comb);
        emit_cand(img, lvl, r, e, keyToFloat(key), reg, anc, HW);
    }
    if (validK < TOPK && t < 32){
        int nfill = TOPK - validK;
        int cum = 0;
        for (int b = 0; b < E && cum < nfill; b += 32){
            int e = b + t;
            bool fail = false;
            if (e < E){
                float sc2 = sqrtf(sigm(cls[(long long)img*E + e]) * sigm(ctr[img*HW + e/NCLS]));
                fail = !(sc2 > SCORE_TH);
            }
            unsigned bal = __ballot_sync(0xFFFFFFFFu, fail);
            int pre = __popc(bal & ((1u << t) - 1u));
            if (fail && cum + pre < nfill)
                emit_cand(img, lvl, validK + cum + pre, e, -1.0f, reg, anc, HW);
            cum += __popc(bal);
        }
    }
}

// ======== K3: binary-search merge of 3 sorted lists + warp NMS + output ========
#define NMT 1024
#define NPT 3
#define OFF_KEY  0
#define OFF_SC   12000
#define OFF_AR   24000
#define OFF_GID  36000
#define OFF_OB   48000
#define OFF_KP   96000
#define OFF_POS  99000
#define OFF_CTL  99400
#define SMEM_NMS 99424

__global__ void __launch_bounds__(NMT, 1)
k_merge_nms(float* __restrict__ out){
    extern __shared__ char dyn[];
    unsigned int*   skey = (unsigned int*)(dyn + OFF_KEY);
    float*          s_sc = (float*)(dyn + OFF_SC);
    float*          s_ar = (float*)(dyn + OFF_AR);
    int*            s_gid= (int*)(dyn + OFF_GID);
    float4*         s_ob = (float4*)(dyn + OFF_OB);
    unsigned char*  kp   = (unsigned char*)(dyn + OFF_KP);
    int*            pos  = (int*)(dyn + OFF_POS);
    int*            ctl  = (int*)(dyn + OFF_CTL);
    cudaGridDependencySynchronize();
    int img = blockIdx.x, t = threadIdx.x;
    int lane = t & 31;

    #pragma unroll
    for (int k = 0; k < NPT; k++){
        int i = t + k*NMT;
        if (i < NCAND){
            skey[i] = fkey(g_score[img*NCAND + i]);
            kp[i] = 0;
        }
    }
    __syncthreads();

    #pragma unroll
    for (int k = 0; k < NPT; k++){
        int i = t + k*NMT;
        if (i < NCAND){
            int L = i / TOPK, r = i - L*TOPK;
            unsigned key = skey[i];
            int m = r;
            #pragma unroll
            for (int M = 0; M < NLEV; M++){
                if (M == L) continue;
                const unsigned* a2 = &skey[M*TOPK];
                int lo = 0, hi = TOPK;
                if (M < L){
                    while (lo < hi){ int mid = (lo+hi)>>1; if (a2[mid] >= key) lo = mid+1; else hi = mid; }
                } else {
                    while (lo < hi){ int mid = (lo+hi)>>1; if (a2[mid] >  key) lo = mid+1; else hi = mid; }
                }
                m += lo;
            }
            s_sc[m]  = keyToFloat(key);
            s_gid[m] = i;
            float4 b = g_box[img*NCAND + i];
            float off = (IMGSZ + 1.0f) * (float)g_label[img*NCAND + i];
            float4 ob = make_float4(b.x+off, b.y+off, b.z+off, b.w+off);
            s_ob[m] = ob;
            s_ar[m] = (ob.z - ob.x) * (ob.w - ob.y);
        }
    }
    __syncthreads();

    if (t < 32){
        float kx0[4], ky0[4], kx1[4], ky1[4], kar[4];
        int cnt = 0;
        float  sc_n = s_sc[0];
        float4 bx_n = s_ob[0];
        float  ax_n = s_ar[0];
        for (int ii = 0; ii < NCAND; ii++){
            float sc = sc_n; float4 bx = bx_n; float ax = ax_n;
            if (ii + 1 < NCAND){ sc_n = s_sc[ii+1]; bx_n = s_ob[ii+1]; ax_n = s_ar[ii+1]; }
            if (!(sc > 0.0f)) break;
            bool sup = false;
            #pragma unroll
            for (int s2 = 0; s2 < 4; s2++){
                if (s2*32 + lane < cnt){
                    float xx0 = fmaxf(bx.x, kx0[s2]), yy0 = fmaxf(bx.y, ky0[s2]);
                    float xx1 = fminf(bx.z, kx1[s2]), yy1 = fminf(bx.w, ky1[s2]);
                    float iw = xx1 - xx0, ih = yy1 - yy0;
                    if (iw > 0.0f && ih > 0.0f){
                        float inter = iw * ih;
                        if (inter / (ax + kar[s2] - inter) > NMS_TH) sup = true;
                    }
                }
            }
            if (__any_sync(0xFFFFFFFFu, sup)) continue;
            if (lane == 0){ pos[cnt] = ii; kp[ii] = 1; }
            if (lane == (cnt & 31)){
                int sl = cnt >> 5;
                if      (sl == 0){ kx0[0]=bx.x; ky0[0]=bx.y; kx1[0]=bx.z; ky1[0]=bx.w; kar[0]=ax; }
                else if (sl == 1){ kx0[1]=bx.x; ky0[1]=bx.y; kx1[1]=bx.z; ky1[1]=bx.w; kar[1]=ax; }
                else if (sl == 2){ kx0[2]=bx.x; ky0[2]=bx.y; kx1[2]=bx.z; ky1[2]=bx.w; kar[2]=ax; }
                else             { kx0[3]=bx.x; ky0[3]=bx.y; kx1[3]=bx.z; ky1[3]=bx.w; kar[3]=ax; }
            }
            cnt++;
            if (cnt >= DETS) break;
        }
        if (lane == 0) ctl[0] = cnt;
    }
    __syncthreads();
    int cntF = ctl[0];
    if (t == 0 && cntF < DETS){
        int fill = cntF;
        for (int p = 0; p < NCAND && fill < DETS; p++)
            if (!kp[p]) pos[fill++] = p;
    }
    __syncthreads();
    if (t < DETS){
        int p = pos[t];
        int gidx = s_gid[p];
        float4 b = g_box[img*NCAND + gidx];
        float* ob = out + (img*DETS + t)*4;
        ob[0] = b.x; ob[1] = b.y; ob[2] = b.z; ob[3] = b.w;
        out[BATCH*DETS*4 + img*DETS + t] = (t < cntF) ? s_sc[p] : -1.0f;
        out[BATCH*DETS*5 + img*DETS + t] = (float)g_label[img*NCAND + gidx];
    }
}

// -------- host: PDL launches --------
static inline void launch_pdl(const void* func, dim3 grid, dim3 block, size_t smem,
                              void** args, bool pdl){
    cudaLaunchConfig_t cfg = {};
    cfg.gridDim = grid; cfg.blockDim = block; cfg.dynamicSmemBytes = smem;
    cudaLaunchAttribute attr[1];
    attr[0].id = cudaLaunchAttributeProgrammaticStreamSerialization;
    attr[0].val.programmaticStreamSerializationAllowed = 1;
    cfg.attrs = attr;
    cfg.numAttrs = pdl ? 1 : 0;
    cudaLaunchKernelExC(&cfg, func, args);
}

extern "C" void kernel_launch(void* const* d_in, const int* in_sizes, int n_in,
                              void* d_out, int out_size){
    const float *cls[3], *reg[3], *ctr[3], *anc[3];
    if (in_sizes[1] == 655360){
        for (int i = 0; i < 3; i++){
            cls[i] = (const float*)d_in[i];
            reg[i] = (const float*)d_in[3 + i];
            ctr[i] = (const float*)d_in[6 + i];
            anc[i] = (const float*)d_in[9 + i];
        }
    } else {
        for (int i = 0; i < 3; i++){
            cls[i] = (const float*)d_in[4*i + 0];
            reg[i] = (const float*)d_in[4*i + 1];
            ctr[i] = (const float*)d_in[4*i + 2];
            anc[i] = (const float*)d_in[4*i + 3];
        }
    }
    float* out = (float*)d_out;

    cudaFuncSetAttribute(k_merge_nms, cudaFuncAttributeMaxDynamicSharedMemorySize, SMEM_NMS);

    int blocks = TOT / (256*EPS);        // 1680

    void* aScore[6] = { &cls[0],&cls[1],&cls[2], &ctr[0],&ctr[1],&ctr[2] };
    void* aLvl[12]  = { &cls[0],&cls[1],&cls[2], &ctr[0],&ctr[1],&ctr[2],
                        &reg[0],&reg[1],&reg[2], &anc[0],&anc[1],&anc[2] };
    void* aNms[1]   = { &out };

    launch_pdl((const void*)k_score,     dim3(blocks), dim3(256), 0, aScore, false);
    launch_pdl((const void*)k_levelsort, dim3(BATCH*NLEV), dim3(1024), 0, aLvl, true);
    launch_pdl((const void*)k_merge_nms, dim3(BATCH), dim3(NMT), SMEM_NMS, aNms, true);
}

// round 16
// speedup vs baseline: 1.2167x; 1.0393x over previous
#include <cuda_runtime.h>
#include <cstdint>

#define BATCH   8
#define NLEV    3
#define NCLS    80
#define TOPK    1000
#define NCAND   3000
#define DETS    100
#define CAPC    32768
#define NBINS   2048
#define IMGSZ   2048.0f
#define SCORE_TH 0.2f
#define NMS_TH   0.6f
#define BIN_SCALE 1152.0f
#define G_HI    (1.0f + (float)NBINS/BIN_SCALE)   /* 2.7778 unchanged */
#define EPT     16           /* fallback path granularity (k_levelsort) */
#define EPS     8            /* k_score elements per thread */
#define SENT    0x7FFFFFFF

#define HW0 4096
#define HW1 1024
#define HW2 256
#define E0  (HW0*NCLS)
#define E1  (HW1*NCLS)
#define E2  (HW2*NCLS)
#define TOT (BATCH*(E0+E1+E2))

typedef unsigned long long ull;

// conservative per-level collection bins (old/8, rounded up: s >= ~0.73 / 0.70 / 0.62)
static __constant__ int c_prebin[NLEV] = { 1010, 1199, 1845 };

// -------- scratch (zero-init; self-cleaned each replay) --------
static __device__ __align__(16) unsigned int g_hist[BATCH*NLEV*NBINS];
static __device__ unsigned int   g_cnt[BATCH*NLEV];
static __device__ ull            g_cand[BATCH*NLEV*CAPC];
static __device__ unsigned short g_binv[BATCH*NLEV*CAPC];
static __device__ float   g_score[BATCH*NCAND];
static __device__ int     g_label[BATCH*NCAND];
static __device__ float4  g_box[BATCH*NCAND];

__device__ __forceinline__ float sigm(float x){ return 1.0f/(1.0f+expf(-x)); }
__device__ __forceinline__ unsigned int fkey(float f){
    unsigned int u = __float_as_uint(f);
    return (u & 0x80000000u) ? ~u : (u | 0x80000000u);
}
__device__ __forceinline__ float keyToFloat(unsigned int k){
    unsigned int u = (k & 0x80000000u) ? (k & 0x7FFFFFFFu) : ~k;
    return __uint_as_float(u);
}
__device__ __forceinline__ int binOf(float g){
    return (int)(fmaxf(g - 1.0f, 0.0f) * BIN_SCALE);
}
__device__ __forceinline__ ull umin64(ull a, ull b){ return a < b ? a : b; }
__device__ __forceinline__ ull umax64(ull a, ull b){ return a > b ? a : b; }

struct Seg { int img, lvl, e, HW, E; };
__device__ __forceinline__ Seg decompose(int gid){
    Seg s;
    if (gid < BATCH*E0){ s.lvl=0; s.img=gid/E0; s.e=gid%E0; s.HW=HW0; s.E=E0; return s; }
    gid -= BATCH*E0;
    if (gid < BATCH*E1){ s.lvl=1; s.img=gid/E1; s.e=gid%E1; s.HW=HW1; s.E=E1; return s; }
    gid -= BATCH*E1;
    s.lvl=2; s.img=gid/E2; s.e=gid%E2; s.HW=HW2; s.E=E2; return s;
}

// ======== K1: 8 elems/thread (max load parallelism); collect bin <= prebin ========
#define SBUF 1024
__global__ void k_score(const float* __restrict__ cls0,const float* __restrict__ cls1,const float* __restrict__ cls2,
                        const float* __restrict__ ctr0,const float* __restrict__ ctr1,const float* __restrict__ ctr2){
    __shared__ ull            sbuf[SBUF];
    __shared__ unsigned short sbin[SBUF];
    __shared__ int sN, sBase;
    int tid = threadIdx.x;
    if (tid == 0) sN = 0;
    __syncthreads();
    int gid = (blockIdx.x*blockDim.x + tid)*EPS;
    Seg S = decompose(gid);              // one block = 2048 contiguous elems, single IL
    const float* cls = (S.lvl==0)?cls0:(S.lvl==1)?cls1:cls2;
    const float* ctr = (S.lvl==0)?ctr0:(S.lvl==1)?ctr1:ctr2;
    int IL = S.img*NLEV + S.lvl;
    size_t ILc = (size_t)IL*CAPC;
    int prebin = c_prebin[S.lvl];
    const float4* cp = reinterpret_cast<const float4*>(&cls[S.img*S.E + S.e]);
    float4 c0 = cp[0], c1 = cp[1];
    int a = S.e / NCLS;                  // 8 | 80 -> group never crosses anchor
    float tval = ctr[S.img*S.HW + a];
    float K = 1.0f + __expf(-tval);
    float gpre = 1.0f + (float)(prebin+1)/BIN_SCALE;
    float q = __fdividef(gpre, K);
    float Tc = (q <= 1.0f) ? 3.0e38f : (-__logf(q - 1.0f) - 1e-3f);
    float cv[EPS] = {c0.x,c0.y,c0.z,c0.w, c1.x,c1.y,c1.z,c1.w};
    unsigned int* H = &g_hist[IL*NBINS];
    int lane = tid & 31;

    unsigned hitmask = 0;
    #pragma unroll
    for (int i = 0; i < EPS; i++){
        if (cv[i] > Tc){
            float g = fmaf(__expf(-cv[i]), K, K);   // exact same bin formula everywhere
            int b = binOf(g);
            if (b <= prebin){
                atomicAdd(&H[b], 1u);
                hitmask |= (1u << i);
            }
        }
    }

    // one warp scan for write positions
    int nloc = __popc(hitmask);
    unsigned incs = (unsigned)nloc;
    #pragma unroll
    for (int o = 1; o < 32; o <<= 1){
        unsigned v = __shfl_up_sync(0xFFFFFFFFu, incs, o);
        if (lane >= o) incs += v;
    }
    int wtot = __shfl_sync(0xFFFFFFFFu, (int)incs, 31);
    int wbase = 0;
    if (wtot){
        if (lane == 31) wbase = atomicAdd(&sN, wtot);
        wbase = __shfl_sync(0xFFFFFFFFu, wbase, 31);
    }
    int p = wbase + (int)incs - nloc;

    if (hitmask){
        #pragma unroll
        for (int i = 0; i < EPS; i++){
            if (hitmask & (1u << i)){
                float g = fmaf(__expf(-cv[i]), K, K);
                int b = binOf(g);
                float sex = sqrtf(sigm(cv[i]) * sigm(tval));   // exact reference score
                ull word = ~(((ull)fkey(sex) << 32) | (unsigned)(0xFFFFFFFFu - (unsigned)(S.e + i)));
                if (p < SBUF){ sbuf[p] = word; sbin[p] = (unsigned short)b; }
                else {
                    unsigned gp2 = atomicAdd(&g_cnt[IL], 1u);    // rare spill
                    if (gp2 < CAPC){ g_cand[ILc + gp2] = word; g_binv[ILc + gp2] = (unsigned short)b; }
                }
                p++;
            }
        }
    }
    __syncthreads();
    int n = min(sN, SBUF);
    if (tid == 0) sBase = (int)atomicAdd(&g_cnt[IL], (unsigned)n);
    __syncthreads();
    int base = sBase;
    for (int i = tid; i < n; i += blockDim.x){
        int gp2 = base + i;
        if (gp2 < CAPC){ g_cand[ILc + gp2] = sbuf[i]; g_binv[ILc + gp2] = sbin[i]; }
    }
}

// decode + clip + store one candidate
__device__ __forceinline__ void emit_cand(int img,int lvl,int r,int e,float score,
                                          const float* reg,const float* anc,int HW){
    int a = e / NCLS, lab = e % NCLS;
    float4 A = reinterpret_cast<const float4*>(anc)[a];
    float4 R = reinterpret_cast<const float4*>(reg)[img*HW + a];
    float cx = 0.5f*(A.x + A.z), cy = 0.5f*(A.y + A.w);
    float w = A.z - A.x, h = A.w - A.y;
    float x0 = fminf(fmaxf(cx - R.x*w, 0.0f), IMGSZ);
    float y0 = fminf(fmaxf(cy - R.y*h, 0.0f), IMGSZ);
    float x1 = fminf(fmaxf(cx + R.z*w, 0.0f), IMGSZ);
    float y1 = fminf(fmaxf(cy + R.w*h, 0.0f), IMGSZ);
    int g = img*NCAND + lvl*TOPK + r;
    g_score[g] = score;
    g_label[g] = lab;
    g_box[g]   = make_float4(x0,y0,x1,y1);
}

__device__ __forceinline__ void reg_substeps(ull &v0, ull &v1, int k, int jhi, int t){
    bool up = (((2*t) & k) == 0);
    for (int j = jhi; j >= 2; j >>= 1){
        int d = j >> 1;
        ull p0 = __shfl_xor_sync(0xFFFFFFFFu, v0, d);
        ull p1 = __shfl_xor_sync(0xFFFFFFFFu, v1, d);
        bool keepmin = (((t & d) == 0) == up);
        v0 = keepmin ? umin64(v0,p0) : umax64(v0,p0);
        v1 = keepmin ? umin64(v1,p1) : umax64(v1,p1);
    }
    ull a = umin64(v0,v1), b = umax64(v0,v1);
    v0 = up ? a : b;
    v1 = up ? b : a;
}

// parallel histogram scan + clean over NBINS=2048 (2 bins/thread); writes bstar into *s_bstar.
__device__ __forceinline__ void hist_scan_clean(unsigned int* h, unsigned* wsum,
                                                volatile int* s_bstar,
                                                int t, int lane, int wid){
    uint2* hv = reinterpret_cast<uint2*>(h + t*2);
    uint2 a0 = hv[0];
    unsigned s = a0.x + a0.y;
    unsigned inc = s;
    #pragma unroll
    for (int o = 1; o < 32; o <<= 1){
        unsigned v = __shfl_up_sync(0xFFFFFFFFu, inc, o);
        if (lane >= o) inc += v;
    }
    if (lane == 31) wsum[wid] = inc;
    __syncthreads();
    if (wid == 0){
        unsigned winc = wsum[lane];
        #pragma unroll
        for (int o = 1; o < 32; o <<= 1){
            unsigned v = __shfl_up_sync(0xFFFFFFFFu, winc, o);
            if (lane >= o) winc += v;
        }
        wsum[lane] = winc;
    }
    __syncthreads();
    unsigned below = ((wid == 0) ? 0u : wsum[wid-1]) + (inc - s);
    if (below < TOPK && below + s >= TOPK){
        *s_bstar = (below + a0.x >= TOPK) ? t*2 : t*2 + 1;
    }
    hv[0] = make_uint2(0u, 0u);
    __syncthreads();
}

// ======== K2: cutoff + compact (or full-rescan fallback) + sort + emit ========
__global__ void __launch_bounds__(1024, 1)
k_levelsort(const float* __restrict__ cls0,const float* __restrict__ cls1,const float* __restrict__ cls2,
            const float* __restrict__ ctr0,const float* __restrict__ ctr1,const float* __restrict__ ctr2,
            const float* __restrict__ reg0,const float* __restrict__ reg1,const float* __restrict__ reg2,
            const float* __restrict__ anc0,const float* __restrict__ anc1,const float* __restrict__ anc2){
    __shared__ ull sh[4096];
    __shared__ unsigned wsum[32];
    __shared__ int s_bstar, s_cnt, s_in;
    cudaGridDependencySynchronize();
    int img = blockIdx.x / NLEV, lvl = blockIdx.x % NLEV;
    int IL = img*NLEV + lvl;
    int t = threadIdx.x, lane = t & 31, wid = t >> 5;
    unsigned int* h = &g_hist[IL*NBINS];

    if (t == 0){
        s_bstar = SENT;
        s_in  = (int)g_cnt[IL];
        g_cnt[IL] = 0u;
        s_cnt = 0;
    }
    __syncthreads();
    hist_scan_clean(h, wsum, &s_bstar, t, lane, wid);
    int bstar = s_bstar;
    int cnt   = s_in;

    const float *reg, *anc, *cls, *ctr; int HW, E;
    if (lvl == 0){ reg=reg0; anc=anc0; cls=cls0; ctr=ctr0; HW=HW0; E=E0; }
    else if (lvl == 1){ reg=reg1; anc=anc1; cls=cls1; ctr=ctr1; HW=HW1; E=E1; }
    else { reg=reg2; anc=anc2; cls=cls2; ctr=ctr2; HW=HW2; E=E2; }

    bool fast = (bstar != SENT) && (bstar <= c_prebin[lvl]) && (cnt <= CAPC);
    size_t ILc = (size_t)IL*CAPC;
    if (fast){
        int n = cnt;
        int nPad = (n + 1023) & ~1023;
        for (int i = t; i < nPad; i += 1024){
            bool keep = (i < n) && (g_binv[ILc + i] <= (unsigned short)bstar);
            ull w = keep ? g_cand[ILc + i] : 0;
            unsigned ball = __ballot_sync(0xFFFFFFFFu, keep);
            int nw = __popc(ball);
            if (nw){
                int bpos = 0;
                if (lane == 0) bpos = atomicAdd(&s_cnt, nw);
                bpos = __shfl_sync(0xFFFFFFFFu, bpos, 0);
                if (keep){
                    int p = bpos + __popc(ball & ((1u << lane) - 1u));
                    if (p < 4096) sh[p] = w;
                }
            }
        }
    } else {
        // ---- fallback (statistically dead, fully correct) ----
        int groups = E / EPT;
        for (int G = t; G < groups; G += 1024){
            int e0 = G*EPT;
            int a = G / 5;                           // 80 = 5*16
            float tval = ctr[img*HW + a];
            float K = 1.0f + __expf(-tval);
            float q2 = __fdividef(G_HI, K);
            float TcF = (q2 <= 1.0f) ? 3.0e38f : (-__logf(q2 - 1.0f) - 1e-3f);
            const float4* cp = reinterpret_cast<const float4*>(&cls[img*E + e0]);
            float4 c0 = cp[0], c1 = cp[1], c2 = cp[2], c3 = cp[3];
            float cv[EPT] = {c0.x,c0.y,c0.z,c0.w, c1.x,c1.y,c1.z,c1.w,
                             c2.x,c2.y,c2.z,c2.w, c3.x,c3.y,c3.z,c3.w};
            #pragma unroll
            for (int i = 0; i < EPT; i++){
                if (cv[i] > TcF){
                    float g = fmaf(__expf(-cv[i]), K, K);
                    int b = binOf(g);
                    if (b < NBINS) atomicAdd(&h[b], 1u);
                }
            }
        }
        __syncthreads();
        if (t == 0) s_bstar = SENT;
        __syncthreads();
        hist_scan_clean(h, wsum, &s_bstar, t, lane, wid);
        bstar = s_bstar;
        for (int G = t; G < groups; G += 1024){
            int e0 = G*EPT;
            int a = G / 5;
            float tval = ctr[img*HW + a];
            float K = 1.0f + __expf(-tval);
            float thrv;
            if (bstar == SENT) thrv = -3.0e38f;
            else {
                float Gm = (1.0f + (float)(bstar+1)/BIN_SCALE) * 1.003f;
                float qr = Gm / K;
                thrv = (qr <= 1.0000012f) ? 3.0e38f : (-logf(qr - 1.0f) - 0.003f);
            }
            const float4* cp = reinterpret_cast<const float4*>(&cls[img*E + e0]);
            float4 c0 = cp[0], c1 = cp[1], c2 = cp[2], c3 = cp[3];
            float cv[EPT] = {c0.x,c0.y,c0.z,c0.w, c1.x,c1.y,c1.z,c1.w,
                             c2.x,c2.y,c2.z,c2.w, c3.x,c3.y,c3.z,c3.w};
            #pragma unroll
            for (int i = 0; i < EPT; i++){
                if (cv[i] > thrv){
                    bool mem = true;
                    if (bstar != SENT){
                        float g = fmaf(__expf(-cv[i]), K, K);
                        mem = (binOf(g) <= bstar);
                    }
                    if (mem){
                        float sex = sqrtf(sigm(cv[i]) * sigm(tval));
                        if (bstar != SENT || sex > SCORE_TH){
                            ull w = ~(((ull)fkey(sex) << 32) | (unsigned)(0xFFFFFFFFu - (unsigned)(e0 + i)));
                            int p = atomicAdd(&s_cnt, 1);
                            if (p < 4096) sh[p] = w;
                        }
                    }
                }
            }
        }
    }
    __syncthreads();
    int C = min(s_cnt, 4096);
    int N = (C <= 1024) ? 1024 : (C <= 2048 ? 2048 : 4096);
    for (int i = C + t; i < N; i += 1024) sh[i] = ~0ULL;
    __syncthreads();

    // ---- hybrid shuffle/smem bitonic sort of N ----
    if (N <= 2048){
        int half = N >> 1;
        ull v0 = 0, v1 = 0;
        if (t < half){
            v0 = sh[2*t]; v1 = sh[2*t+1];
            #pragma unroll
            for (int k = 2; k <= 64; k <<= 1)
                reg_substeps(v0, v1, k, (k>>1) >= 2 ? (k>>1) : 0, t);
            sh[2*t] = v0; sh[2*t+1] = v1;
        }
        __syncthreads();
        for (int k = 128; k <= N; k <<= 1){
            for (int j = k>>1; j >= 64; j >>= 1){
                for (int i = t; i < N; i += 1024){
                    int l = i ^ j;
                    if (l > i){
                        ull a = sh[i], b = sh[l];
                        bool up = ((i & k) == 0);
                        if ((a > b) == up){ sh[i] = b; sh[l] = a; }
                    }
                }
                __syncthreads();
            }
            if (t < half){
                v0 = sh[2*t]; v1 = sh[2*t+1];
                reg_substeps(v0, v1, k, 32, t);
                sh[2*t] = v0; sh[2*t+1] = v1;
            }
            __syncthreads();
        }
    } else {
        for (int k = 2; k <= N; k <<= 1)
            for (int j = k>>1; j > 0; j >>= 1){
                for (int i = t; i < N; i += 1024){
                    int l = i ^ j;
                    if (l > i){
                        ull a = sh[i], b = sh[l];
                        bool up = ((i & k) == 0);
                        if ((a > b) == up){ sh[i] = b; sh[l] = a; }
                    }
                }
                __syncthreads();
            }
    }

    int validK = min(C, TOPK);
    for (int r = t; r < validK; r += 1024){
        ull comb = ~sh[r];
        unsigned key = (unsigned)(comb >> 32);
        int e = (int)(0xFFFFFFFFu - (unsigned)comb);
        emit_cand(img, lvl, r, e, keyToFloat(key), reg, anc, HW);
    }
    if (validK < TOPK && t < 32){
        int nfill = TOPK - validK;
        int cum = 0;
        for (int b = 0; b < E && cum < nfill; b += 32){
            int e = b + t;
            bool fail = false;
            if (e < E){
                float sc2 = sqrtf(sigm(cls[(long long)img*E + e]) * sigm(ctr[img*HW + e/NCLS]));
                fail = !(sc2 > SCORE_TH);
            }
            unsigned bal = __ballot_sync(0xFFFFFFFFu, fail);
            int pre = __popc(bal & ((1u << t) - 1u));
            if (fail && cum + pre < nfill)
                emit_cand(img, lvl, validK + cum + pre, e, -1.0f, reg, anc, HW);
            cum += __popc(bal);
        }
    }
}

// ======== K3: binary-search merge of 3 sorted lists + warp NMS + output ========
#define NMT 1024
#define NPT 3
#define OFF_KEY  0
#define OFF_SC   12000
#define OFF_AR   24000
#define OFF_GID  36000
#define OFF_OB   48000
#define OFF_KP   96000
#define OFF_POS  99000
#define OFF_CTL  99400
#define SMEM_NMS 99424

__global__ void __launch_bounds__(NMT, 1)
k_merge_nms(float* __restrict__ out){
    extern __shared__ char dyn[];
    unsigned int*   skey = (unsigned int*)(dyn + OFF_KEY);
    float*          s_sc = (float*)(dyn + OFF_SC);
    float*          s_ar = (float*)(dyn + OFF_AR);
    int*            s_gid= (int*)(dyn + OFF_GID);
    float4*         s_ob = (float4*)(dyn + OFF_OB);
    unsigned char*  kp   = (unsigned char*)(dyn + OFF_KP);
    int*            pos  = (int*)(dyn + OFF_POS);
    int*            ctl  = (int*)(dyn + OFF_CTL);
    cudaGridDependencySynchronize();
    int img = blockIdx.x, t = threadIdx.x;
    int lane = t & 31;

    #pragma unroll
    for (int k = 0; k < NPT; k++){
        int i = t + k*NMT;
        if (i < NCAND){
            skey[i] = fkey(g_score[img*NCAND + i]);
            kp[i] = 0;
        }
    }
    __syncthreads();

    #pragma unroll
    for (int k = 0; k < NPT; k++){
        int i = t + k*NMT;
        if (i < NCAND){
            int L = i / TOPK, r = i - L*TOPK;
            unsigned key = skey[i];
            int m = r;
            #pragma unroll
            for (int M = 0; M < NLEV; M++){
                if (M == L) continue;
                const unsigned* a2 = &skey[M*TOPK];
                int lo = 0, hi = TOPK;
                if (M < L){
                    while (lo < hi){ int mid = (lo+hi)>>1; if (a2[mid] >= key) lo = mid+1; else hi = mid; }
                } else {
                    while (lo < hi){ int mid = (lo+hi)>>1; if (a2[mid] >  key) lo = mid+1; else hi = mid; }
                }
                m += lo;
            }
            s_sc[m]  = keyToFloat(key);
            s_gid[m] = i;
            float4 b = g_box[img*NCAND + i];
            float off = (IMGSZ + 1.0f) * (float)g_label[img*NCAND + i];
            float4 ob = make_float4(b.x+off, b.y+off, b.z+off, b.w+off);
            s_ob[m] = ob;
            s_ar[m] = (ob.z - ob.x) * (ob.w - ob.y);
        }
    }
    __syncthreads();

    if (t < 32){
        float kx0[4], ky0[4], kx1[4], ky1[4], kar[4];
        int cnt = 0;
        float  sc_n = s_sc[0];
        float4 bx_n = s_ob[0];
        float  ax_n = s_ar[0];
        for (int ii = 0; ii < NCAND; ii++){
            float sc = sc_n; float4 bx = bx_n; float ax = ax_n;
            if (ii + 1 < NCAND){ sc_n = s_sc[ii+1]; bx_n = s_ob[ii+1]; ax_n = s_ar[ii+1]; }
            if (!(sc > 0.0f)) break;
            bool sup = false;
            #pragma unroll
            for (int s2 = 0; s2 < 4; s2++){
                if (s2*32 + lane < cnt){
                    float xx0 = fmaxf(bx.x, kx0[s2]), yy0 = fmaxf(bx.y, ky0[s2]);
                    float xx1 = fminf(bx.z, kx1[s2]), yy1 = fminf(bx.w, ky1[s2]);
                    float iw = xx1 - xx0, ih = yy1 - yy0;
                    if (iw > 0.0f && ih > 0.0f){
                        float inter = iw * ih;
                        if (inter / (ax + kar[s2] - inter) > NMS_TH) sup = true;
                    }
                }
            }
            if (__any_sync(0xFFFFFFFFu, sup)) continue;
            if (lane == 0){ pos[cnt] = ii; kp[ii] = 1; }
            if (lane == (cnt & 31)){
                int sl = cnt >> 5;
                if      (sl == 0){ kx0[0]=bx.x; ky0[0]=bx.y; kx1[0]=bx.z; ky1[0]=bx.w; kar[0]=ax; }
                else if (sl == 1){ kx0[1]=bx.x; ky0[1]=bx.y; kx1[1]=bx.z; ky1[1]=bx.w; kar[1]=ax; }
                else if (sl == 2){ kx0[2]=bx.x; ky0[2]=bx.y; kx1[2]=bx.z; ky1[2]=bx.w; kar[2]=ax; }
                else             { kx0[3]=bx.x; ky0[3]=bx.y; kx1[3]=bx.z; ky1[3]=bx.w; kar[3]=ax; }
            }
            cnt++;
            if (cnt >= DETS) break;
        }
        if (lane == 0) ctl[0] = cnt;
    }
    __syncthreads();
    int cntF = ctl[0];
    if (t == 0 && cntF < DETS){
        int fill = cntF;
        for (int p = 0; p < NCAND && fill < DETS; p++)
            if (!kp[p]) pos[fill++] = p;
    }
    __syncthreads();
    if (t < DETS){
        int p = pos[t];
        int gidx = s_gid[p];
        float4 b = g_box[img*NCAND + gidx];
        float* ob = out + (img*DETS + t)*4;
        ob[0] = b.x; ob[1] = b.y; ob[2] = b.z; ob[3] = b.w;
        out[BATCH*DETS*4 + img*DETS + t] = (t < cntF) ? s_sc[p] : -1.0f;
        out[BATCH*DETS*5 + img*DETS + t] = (float)g_label[img*NCAND + gidx];
    }
}

// -------- host: PDL launches --------
static inline void launch_pdl(const void* func, dim3 grid, dim3 block, size_t smem,
                              void** args, bool pdl){
    cudaLaunchConfig_t cfg = {};
    cfg.gridDim = grid; cfg.blockDim = block; cfg.dynamicSmemBytes = smem;
    cudaLaunchAttribute attr[1];
    attr[0].id = cudaLaunchAttributeProgrammaticStreamSerialization;
    attr[0].val.programmaticStreamSerializationAllowed = 1;
    cfg.attrs = attr;
    cfg.numAttrs = pdl ? 1 : 0;
    cudaLaunchKernelExC(&cfg, func, args);
}

extern "C" void kernel_launch(void* const* d_in, const int* in_sizes, int n_in,
                              void* d_out, int out_size){
    const float *cls[3], *reg[3], *ctr[3], *anc[3];
    if (in_sizes[1] == 655360){
        for (int i = 0; i < 3; i++){
            cls[i] = (const float*)d_in[i];
            reg[i] = (const float*)d_in[3 + i];
            ctr[i] = (const float*)d_in[6 + i];
            anc[i] = (const float*)d_in[9 + i];
        }
    } else {
        for (int i = 0; i < 3; i++){
            cls[i] = (const float*)d_in[4*i + 0];
            reg[i] = (const float*)d_in[4*i + 1];
            ctr[i] = (const float*)d_in[4*i + 2];
            anc[i] = (const float*)d_in[4*i + 3];
        }
    }
    float* out = (float*)d_out;

    cudaFuncSetAttribute(k_merge_nms, cudaFuncAttributeMaxDynamicSharedMemorySize, SMEM_NMS);

    int blocks = TOT / (256*EPS);        // 1680

    void* aScore[6] = { &cls[0],&cls[1],&cls[2], &ctr[0],&ctr[1],&ctr[2] };
    void* aLvl[12]  = { &cls[0],&cls[1],&cls[2], &ctr[0],&ctr[1],&ctr[2],
                        &reg[0],&reg[1],&reg[2], &anc[0],&anc[1],&anc[2] };
    void* aNms[1]   = { &out };

    launch_pdl((const void*)k_score,     dim3(blocks), dim3(256), 0, aScore, false);
    launch_pdl((const void*)k_levelsort, dim3(BATCH*NLEV), dim3(1024), 0, aLvl, true);
    launch_pdl((const void*)k_merge_nms, dim3(BATCH), dim3(NMT), SMEM_NMS, aNms, true);
}